// round 8
// baseline (speedup 1.0000x reference)
#include <cuda_runtime.h>
#include <cuda_fp16.h>
#include <cstdint>

// Shapes
#define Bb 4
#define Ll 48
#define LP 96
#define Nn 512
#define Dd 128
#define DF 512
#define Hh 8
#define HD 16

#define M1 (Bb*Ll*Nn)    // 98304
#define M2 (Bb*LP*Nn)    // 196608
#define BLn (Bb*Ll)      // 192

// ---------------- scratch (static device memory; no allocations) ----------------
__device__ float g_q [M1*Dd];
__device__ float g_k [M2*Dd];
__device__ float g_v [M2*Dd];
__device__ float g_t [M1*Dd];
__device__ float g_h [M1*Dd];
__device__ float g_xn[M1*Dd];
__device__ float g_y [M1*Dd];
__device__ float g_go[(long long)BLn*Dd*Nn];        // gout fp32
__device__ __half g_bigH[(long long)M1*DF];         // y1 (fp16), then A-adj (fp16)
__device__ __half g_HbH[(long long)BLn*640*Nn];     // Hc fp16: [192][640][512]
__device__ __half g_supH[Nn*Nn];                    // support fp16

__device__ __forceinline__ uint32_t h2u(__half2 h) {
    uint32_t u;
    memcpy(&u, &h, 4);
    return u;
}

// ---------------- FP16 tensor-core GEMM: C = A@B (+bias)(+relu), batched ----------------
// A[M,K], B[K,N], C[M,N]. aH/bH/cH select fp16 storage for A/B/C (fp32 otherwise).
// 128x128 tile, k-step 32, 8 warps, fp32 accumulate.
// Per batch z: A += (modA? z%modA : z)*sA ; B += z*sB ; C += z*sC (element strides).
__global__ void __launch_bounds__(256) hgemm_kernel(
    const void* __restrict__ Av, const void* __restrict__ Bv, void* __restrict__ Cv,
    int M, int N, int K,
    long long sA, long long sB, long long sC, int modA,
    const float* __restrict__ bias, int doRelu, int aH, int bH, int cH)
{
    __shared__ uint32_t As2[128][18];   // half2 bits [m][k/2]
    __shared__ uint32_t Bs2[128][18];   // half2 bits [n][k/2]

    int z = blockIdx.z;
    long long za = (modA > 0 ? (z % modA) : z);

    int tid  = threadIdx.x;
    int warp = tid >> 5;
    int lane = tid & 31;
    int wm = warp >> 2;
    int wn = warp & 3;
    int lr = lane >> 2;
    int lc = lane & 3;

    int brow = blockIdx.y * 128;
    int bcol = blockIdx.x * 128;

    int rA = tid >> 3;            // 0..31
    int cA = (tid & 7) * 4;       // 0..28
    int nB = tid & 127;
    int kqB = tid >> 7;           // 0..1

    float acc[4][4][4];
    #pragma unroll
    for (int i = 0; i < 4; i++)
        #pragma unroll
        for (int j = 0; j < 4; j++)
            #pragma unroll
            for (int r = 0; r < 4; r++) acc[i][j][r] = 0.f;

    const float*  Af = (const float*)Av  + za * sA;
    const __half* Ah = (const __half*)Av + za * sA;
    const float*  Bf = (const float*)Bv  + (long long)z * sB;
    const __half* Bh = (const __half*)Bv + (long long)z * sB;

    for (int k0 = 0; k0 < K; k0 += 32) {
        // ---- stage A tile 128x32 ----
        if (aH) {
            #pragma unroll
            for (int u = 0; u < 4; u++) {
                int r = rA + u * 32;
                uint2 pk = *(const uint2*)(Ah + (long long)(brow + r) * K + k0 + cA);
                *(uint2*)&As2[r][cA >> 1] = pk;
            }
        } else {
            #pragma unroll
            for (int u = 0; u < 4; u++) {
                int r = rA + u * 32;
                float4 va = *(const float4*)(Af + (long long)(brow + r) * K + k0 + cA);
                uint2 pk = make_uint2(h2u(__floats2half2_rn(va.x, va.y)),
                                      h2u(__floats2half2_rn(va.z, va.w)));
                *(uint2*)&As2[r][cA >> 1] = pk;
            }
        }
        // ---- stage B tile 32x128 (transpose during STS) ----
        if (bH) {
            #pragma unroll
            for (int u = 0; u < 4; u++) {
                int kq = kqB + u * 2;
                int kk = k0 + kq * 4;
                const __half* bp = Bh + (long long)kk * N + bcol + nB;
                __half b0 = bp[0], b1 = bp[N], b2 = bp[2*N], b3 = bp[3*N];
                uint2 pk = make_uint2(h2u(__halves2half2(b0, b1)),
                                      h2u(__halves2half2(b2, b3)));
                *(uint2*)&Bs2[nB][kq << 1] = pk;
            }
        } else {
            #pragma unroll
            for (int u = 0; u < 4; u++) {
                int kq = kqB + u * 2;
                int kk = k0 + kq * 4;
                const float* bp = Bf + (long long)kk * N + bcol + nB;
                float f0 = bp[0], f1 = bp[N], f2 = bp[2*N], f3 = bp[3*N];
                uint2 pk = make_uint2(h2u(__floats2half2_rn(f0, f1)),
                                      h2u(__floats2half2_rn(f2, f3)));
                *(uint2*)&Bs2[nB][kq << 1] = pk;
            }
        }
        __syncthreads();

        #pragma unroll
        for (int kk = 0; kk < 2; kk++) {
            int kb = kk * 8;
            uint32_t a[4][4], b[4][2];
            #pragma unroll
            for (int mf = 0; mf < 4; mf++) {
                int row = wm*64 + mf*16 + lr;
                a[mf][0] = As2[row  ][kb + lc];
                a[mf][1] = As2[row+8][kb + lc];
                a[mf][2] = As2[row  ][kb + lc + 4];
                a[mf][3] = As2[row+8][kb + lc + 4];
            }
            #pragma unroll
            for (int nf = 0; nf < 4; nf++) {
                int col = wn*32 + nf*8 + lr;
                b[nf][0] = Bs2[col][kb + lc];
                b[nf][1] = Bs2[col][kb + lc + 4];
            }
            #pragma unroll
            for (int mf = 0; mf < 4; mf++)
                #pragma unroll
                for (int nf = 0; nf < 4; nf++) {
                    asm volatile(
                        "mma.sync.aligned.m16n8k16.row.col.f32.f16.f16.f32 "
                        "{%0,%1,%2,%3}, {%4,%5,%6,%7}, {%8,%9}, {%0,%1,%2,%3};\n"
                        : "+f"(acc[mf][nf][0]), "+f"(acc[mf][nf][1]),
                          "+f"(acc[mf][nf][2]), "+f"(acc[mf][nf][3])
                        : "r"(a[mf][0]), "r"(a[mf][1]), "r"(a[mf][2]), "r"(a[mf][3]),
                          "r"(b[nf][0]), "r"(b[nf][1]));
                }
        }
        __syncthreads();
    }

    // epilogue
    float*  Cf = (float*)Cv  + (long long)z * sC;
    __half* Ch = (__half*)Cv + (long long)z * sC;
    #pragma unroll
    for (int mf = 0; mf < 4; mf++) {
        int row0 = brow + wm*64 + mf*16 + lr;
        #pragma unroll
        for (int nf = 0; nf < 4; nf++) {
            int col = bcol + wn*32 + nf*8 + lc*2;
            float bx = 0.f, by = 0.f;
            if (bias) { bx = bias[col]; by = bias[col+1]; }
            float v0 = acc[mf][nf][0] + bx;
            float v1 = acc[mf][nf][1] + by;
            float v2 = acc[mf][nf][2] + bx;
            float v3 = acc[mf][nf][3] + by;
            if (doRelu) {
                v0 = fmaxf(v0, 0.f); v1 = fmaxf(v1, 0.f);
                v2 = fmaxf(v2, 0.f); v3 = fmaxf(v3, 0.f);
            }
            if (cH) {
                *(__half2*)(Ch + (long long)row0*N + col)     = __floats2half2_rn(v0, v1);
                *(__half2*)(Ch + (long long)(row0+8)*N + col) = __floats2half2_rn(v2, v3);
            } else {
                *(float2*)(Cf + (long long)row0*N + col)     = make_float2(v0, v1);
                *(float2*)(Cf + (long long)(row0+8)*N + col) = make_float2(v2, v3);
            }
        }
    }
}

// ---------------- attention: one block per (b, n, h), 256 threads ----------------
#define STP 52
__global__ void __launch_bounds__(256) attn_kernel(
    const float* __restrict__ Q, const float* __restrict__ Kt, const float* __restrict__ V,
    float* __restrict__ O, int Lq, int Lk)
{
    __shared__ float Qs[48*20];
    __shared__ float Ks[96*20];
    __shared__ float Vs[96*20];
    __shared__ float St[96*STP];   // [m][l]

    int bid = blockIdx.x;
    int h = bid & 7;
    int n = (bid >> 3) & (Nn - 1);
    int b = bid >> 12;
    int tid = threadIdx.x;

    for (int i = tid; i < Lq*4; i += 256) {
        int l = i >> 2, j4 = i & 3;
        *(float4*)&Qs[l*20 + j4*4] =
            *(const float4*)(Q + (((long long)(b*Lq + l))*Nn + n)*Dd + h*HD + j4*4);
    }
    for (int i = tid; i < Lk*4; i += 256) {
        int m = i >> 2, j4 = i & 3;
        long long base = (((long long)(b*Lk + m))*Nn + n)*Dd + h*HD + j4*4;
        *(float4*)&Ks[m*20 + j4*4] = *(const float4*)(Kt + base);
        *(float4*)&Vs[m*20 + j4*4] = *(const float4*)(V + base);
    }
    __syncthreads();

    const float scale = 0.25f;  // 1/sqrt(16)
    int tlc = Lq >> 1, tmc = Lk >> 2;
    for (int t = tid; t < tlc*tmc; t += 256) {
        int tl = t / tmc, tm = t - tl*tmc;
        int l0 = tl*2, m0 = tm*4;
        const float4* q0 = (const float4*)&Qs[l0*20];
        const float4* q1 = (const float4*)&Qs[(l0+1)*20];
        float4 qa0 = q0[0], qa1 = q0[1], qa2 = q0[2], qa3 = q0[3];
        float4 qb0 = q1[0], qb1 = q1[1], qb2 = q1[2], qb3 = q1[3];
        #pragma unroll
        for (int mi = 0; mi < 4; mi++) {
            const float4* kp = (const float4*)&Ks[(m0+mi)*20];
            float4 k0 = kp[0], k1 = kp[1], k2 = kp[2], k3 = kp[3];
            float sA = 0.f, sB = 0.f;
            sA = fmaf(qa0.x,k0.x,sA); sA = fmaf(qa0.y,k0.y,sA); sA = fmaf(qa0.z,k0.z,sA); sA = fmaf(qa0.w,k0.w,sA);
            sA = fmaf(qa1.x,k1.x,sA); sA = fmaf(qa1.y,k1.y,sA); sA = fmaf(qa1.z,k1.z,sA); sA = fmaf(qa1.w,k1.w,sA);
            sA = fmaf(qa2.x,k2.x,sA); sA = fmaf(qa2.y,k2.y,sA); sA = fmaf(qa2.z,k2.z,sA); sA = fmaf(qa2.w,k2.w,sA);
            sA = fmaf(qa3.x,k3.x,sA); sA = fmaf(qa3.y,k3.y,sA); sA = fmaf(qa3.z,k3.z,sA); sA = fmaf(qa3.w,k3.w,sA);
            sB = fmaf(qb0.x,k0.x,sB); sB = fmaf(qb0.y,k0.y,sB); sB = fmaf(qb0.z,k0.z,sB); sB = fmaf(qb0.w,k0.w,sB);
            sB = fmaf(qb1.x,k1.x,sB); sB = fmaf(qb1.y,k1.y,sB); sB = fmaf(qb1.z,k1.z,sB); sB = fmaf(qb1.w,k1.w,sB);
            sB = fmaf(qb2.x,k2.x,sB); sB = fmaf(qb2.y,k2.y,sB); sB = fmaf(qb2.z,k2.z,sB); sB = fmaf(qb2.w,k2.w,sB);
            sB = fmaf(qb3.x,k3.x,sB); sB = fmaf(qb3.y,k3.y,sB); sB = fmaf(qb3.z,k3.z,sB); sB = fmaf(qb3.w,k3.w,sB);
            St[(m0+mi)*STP + l0]     = sA * scale;
            St[(m0+mi)*STP + l0 + 1] = sB * scale;
        }
    }
    __syncthreads();

    if (tid < Lq) {
        float mx = -1e30f;
        for (int m = 0; m < Lk; m++) mx = fmaxf(mx, St[m*STP + tid]);
        float sum = 0.f;
        for (int m = 0; m < Lk; m++) {
            float e = __expf(St[m*STP + tid] - mx);
            St[m*STP + tid] = e;
            sum += e;
        }
        float inv = 1.f / sum;
        for (int m = 0; m < Lk; m++) St[m*STP + tid] *= inv;
    }
    __syncthreads();

    // AV: 192 active threads (1 l, 4-col float4 each); St scalar reads broadcast
    if (tid < Lq * 4) {
        int l = tid >> 2, j4 = tid & 3;
        float4 a = make_float4(0.f, 0.f, 0.f, 0.f);
        #pragma unroll 4
        for (int m = 0; m < Lk; m++) {
            float w = St[m*STP + l];
            float4 v = *(const float4*)&Vs[m*20 + j4*4];
            a.x = fmaf(w, v.x, a.x);
            a.y = fmaf(w, v.y, a.y);
            a.z = fmaf(w, v.z, a.z);
            a.w = fmaf(w, v.w, a.w);
        }
        *(float4*)(O + (((long long)(b*Lq + l))*Nn + n)*Dd + h*HD + j4*4) = a;
    }
}

// ---------------- fused residual add + LayerNorm ----------------
__global__ void __launch_bounds__(256) ln_add_kernel(
    float* __restrict__ out, const float* __restrict__ X, const float* __restrict__ P,
    const float* __restrict__ g, const float* __restrict__ bta, int rows)
{
    int row  = (blockIdx.x * 256 + threadIdx.x) >> 5;
    int lane = threadIdx.x & 31;
    if (row >= rows) return;
    long long base = (long long)row * Dd + lane*4;
    float4 a = *(const float4*)(X + base);
    float4 p = *(const float4*)(P + base);
    float v0 = a.x+p.x, v1 = a.y+p.y, v2 = a.z+p.z, v3 = a.w+p.w;
    float s  = v0+v1+v2+v3;
    float s2 = v0*v0+v1*v1+v2*v2+v3*v3;
    #pragma unroll
    for (int o = 16; o; o >>= 1) {
        s  += __shfl_xor_sync(0xffffffffu, s,  o);
        s2 += __shfl_xor_sync(0xffffffffu, s2, o);
    }
    float mu  = s * (1.f/128.f);
    float var = s2 * (1.f/128.f) - mu*mu;
    float rs  = rsqrtf(var + 1e-5f);
    float4 gg = *(const float4*)(g   + lane*4);
    float4 bb = *(const float4*)(bta + lane*4);
    float4 o4;
    o4.x = (v0-mu)*rs*gg.x + bb.x;
    o4.y = (v1-mu)*rs*gg.y + bb.y;
    o4.z = (v2-mu)*rs*gg.z + bb.z;
    o4.w = (v3-mu)*rs*gg.w + bb.w;
    *(float4*)(out + base) = o4;
}

// ---------------- transpose data[bl] [512,128] -> fp16 g0 rows of Hc [128,512] ----------------
__global__ void transpose_g0_kernel(const float* __restrict__ in, __half* __restrict__ out)
{
    __shared__ float t[32][33];
    int bl = blockIdx.z;
    int n0 = blockIdx.x * 32;
    int c0 = blockIdx.y * 32;
    const float* ip = in  + (long long)bl * (Nn*Dd);
    __half*      op = out + (long long)bl * (640*Nn);
    #pragma unroll
    for (int j = 0; j < 32; j += 8)
        t[threadIdx.y + j][threadIdx.x] = ip[(n0 + threadIdx.y + j)*Dd + c0 + threadIdx.x];
    __syncthreads();
    #pragma unroll
    for (int j = 0; j < 32; j += 8)
        op[(c0 + threadIdx.y + j)*Nn + n0 + threadIdx.x] = __float2half(t[threadIdx.x][threadIdx.y + j]);
}

// ---------------- transpose gout[bl] [128,512] + gcn_b -> dts [512,128] ----------------
__global__ void transpose_gout_kernel(const float* __restrict__ in, const float* __restrict__ gb,
                                      float* __restrict__ out)
{
    __shared__ float t[32][33];
    int bl = blockIdx.z;
    int l  = bl % Ll;
    int n0 = blockIdx.x * 32;
    int o0 = blockIdx.y * 32;
    const float* ip = in  + (long long)bl * (Dd*Nn);
    float*       op = out + (long long)bl * (Nn*Dd);
    #pragma unroll
    for (int j = 0; j < 32; j += 8)
        t[threadIdx.y + j][threadIdx.x] = ip[(o0 + threadIdx.y + j)*Nn + n0 + threadIdx.x];
    __syncthreads();
    #pragma unroll
    for (int j = 0; j < 32; j += 8) {
        int o = o0 + threadIdx.x;
        op[(n0 + threadIdx.y + j)*Dd + o] = t[threadIdx.x][threadIdx.y + j] + gb[l*Dd + o];
    }
}

// ---------------- fp32 -> fp16 convert ----------------
__global__ void f2h_kernel(const float* __restrict__ in, __half* __restrict__ out, int n4)
{
    int i = blockIdx.x * 256 + threadIdx.x;
    if (i < n4) {
        float4 v = ((const float4*)in)[i];
        __half2 h0 = __floats2half2_rn(v.x, v.y);
        __half2 h1 = __floats2half2_rn(v.z, v.w);
        uint2 pk = make_uint2(h2u(h0), h2u(h1));
        ((uint2*)out)[i] = pk;
    }
}

// ---------------- host ----------------
static inline void gemm(const void* A, const void* B, void* C, int M, int N, int K,
                        long long sA, long long sB, long long sC, int batch, int modA,
                        const float* bias, int relu, int aH, int bH, int cH)
{
    dim3 grid(N/128, M/128, batch);
    hgemm_kernel<<<grid, 256>>>(A, B, C, M, N, K, sA, sB, sC, modA, bias, relu, aH, bH, cH);
}

extern "C" void kernel_launch(void* const* d_in, const int* in_sizes, int n_in,
                              void* d_out, int out_size)
{
    const float* x       = (const float*)d_in[0];
    const float* memory  = (const float*)d_in[1];
    const float* data    = (const float*)d_in[2];
    const float* support = (const float*)d_in[3];
    const float* Wq_s = (const float*)d_in[4];
    const float* Wk_s = (const float*)d_in[5];
    const float* Wv_s = (const float*)d_in[6];
    const float* Wo_s = (const float*)d_in[7];
    const float* Wq_c = (const float*)d_in[8];
    const float* Wk_c = (const float*)d_in[9];
    const float* Wv_c = (const float*)d_in[10];
    const float* Wo_c = (const float*)d_in[11];
    const float* W1   = (const float*)d_in[12];
    const float* b1   = (const float*)d_in[13];
    const float* W2   = (const float*)d_in[14];
    const float* b2   = (const float*)d_in[15];
    const float* W3   = (const float*)d_in[16];
    const float* b3   = (const float*)d_in[17];
    const float* gcnW = (const float*)d_in[18];
    const float* gcnB = (const float*)d_in[19];
    const float* ln1g = (const float*)d_in[20];
    const float* ln1b = (const float*)d_in[21];
    const float* ln2g = (const float*)d_in[22];
    const float* ln2b = (const float*)d_in[23];
    const float* ln3g = (const float*)d_in[24];
    const float* ln3b = (const float*)d_in[25];

    float *q, *k, *v, *t, *h, *xn, *y, *go;
    __half *bigH, *HbH, *supH;
    cudaGetSymbolAddress((void**)&q,  g_q);
    cudaGetSymbolAddress((void**)&k,  g_k);
    cudaGetSymbolAddress((void**)&v,  g_v);
    cudaGetSymbolAddress((void**)&t,  g_t);
    cudaGetSymbolAddress((void**)&h,  g_h);
    cudaGetSymbolAddress((void**)&xn, g_xn);
    cudaGetSymbolAddress((void**)&y,  g_y);
    cudaGetSymbolAddress((void**)&go, g_go);
    cudaGetSymbolAddress((void**)&bigH, g_bigH);
    cudaGetSymbolAddress((void**)&HbH, g_HbH);
    cudaGetSymbolAddress((void**)&supH, g_supH);

    float* out1 = (float*)d_out;               // LN3(xn + y)
    float* out2 = out1 + (long long)M1 * Dd;   // dts

    const int nLnBlocks = M1 / 8;

    // support -> fp16 (tiny, done up front)
    f2h_kernel<<<(Nn*Nn/4 + 255)/256, 256>>>(support, supH, Nn*Nn/4);

    // ---- self-attention ----
    gemm(x, Wq_s, q, M1, Dd, Dd, 0,0,0, 1,0, nullptr, 0, 0,0,0);
    gemm(x, Wk_s, k, M1, Dd, Dd, 0,0,0, 1,0, nullptr, 0, 0,0,0);
    gemm(x, Wv_s, v, M1, Dd, Dd, 0,0,0, 1,0, nullptr, 0, 0,0,0);
    attn_kernel<<<Bb*Nn*Hh, 256>>>(q, k, v, t, Ll, Ll);
    gemm(t, Wo_s, q, M1, Dd, Dd, 0,0,0, 1,0, nullptr, 0, 0,0,0);
    ln_add_kernel<<<nLnBlocks, 256>>>(h, x, q, ln1g, ln1b, M1);

    // ---- cross-attention ----
    gemm(h,      Wq_c, t, M1, Dd, Dd, 0,0,0, 1,0, nullptr, 0, 0,0,0);
    gemm(memory, Wk_c, k, M2, Dd, Dd, 0,0,0, 1,0, nullptr, 0, 0,0,0);
    gemm(memory, Wv_c, v, M2, Dd, Dd, 0,0,0, 1,0, nullptr, 0, 0,0,0);
    attn_kernel<<<Bb*Nn*Hh, 256>>>(t, k, v, q, Ll, LP);
    gemm(q, Wo_c, t, M1, Dd, Dd, 0,0,0, 1,0, nullptr, 0, 0,0,0);
    ln_add_kernel<<<nLnBlocks, 256>>>(xn, h, t, ln2g, ln2b, M1);

    // ---- FFN (hidden y1 kept in fp16) ----
    gemm(xn,   W1, bigH, M1, DF, Dd, 0,0,0, 1,0, b1, 1, 0,0,1);
    gemm(bigH, W2, y,    M1, Dd, DF, 0,0,0, 1,0, b2, 0, 1,0,0);
    ln_add_kernel<<<nLnBlocks, 256>>>(out1, xn, y, ln3g, ln3b, M1);

    // ---- dynamic adjacency A = y@W3 + b3 (fp16, reuses bigH after FFN2 consumed y1) ----
    gemm(y, W3, bigH, M1, Nn, Dd, 0,0,0, 1,0, b3, 0, 0,0,1);

    // ---- GCN (all intermediates fp16) ----
    transpose_g0_kernel<<<dim3(16,4,BLn), dim3(32,8)>>>(data, HbH);
    gemm(HbH,          supH, HbH +  65536, 128, Nn, Nn, 327680LL, 0,        327680LL, BLn, 0, nullptr, 0, 1,1,1);
    gemm(HbH,          bigH, HbH + 196608, 128, Nn, Nn, 327680LL, 262144LL, 327680LL, BLn, 0, nullptr, 0, 1,1,1);
    gemm(HbH +  65536, supH, HbH + 131072, 128, Nn, Nn, 327680LL, 0,        327680LL, BLn, 0, nullptr, 0, 1,1,1);
    gemm(HbH + 196608, bigH, HbH + 262144, 128, Nn, Nn, 327680LL, 262144LL, 327680LL, BLn, 0, nullptr, 0, 1,1,1);
    gemm(gcnW, HbH, go, 128, Nn, 5*Dd, 81920LL, 327680LL, 65536LL, BLn, Ll, nullptr, 0, 0,1,0);
    transpose_gout_kernel<<<dim3(16,4,BLn), dim3(32,8)>>>(go, gcnB, out2);
}

// round 9
// speedup vs baseline: 1.3144x; 1.3144x over previous
#include <cuda_runtime.h>
#include <cuda_fp16.h>
#include <cstdint>

// Shapes
#define Bb 4
#define Ll 48
#define LP 96
#define Nn 512
#define Dd 128
#define DF 512
#define Hh 8
#define HD 16

#define M1 (Bb*Ll*Nn)    // 98304
#define M2 (Bb*LP*Nn)    // 196608
#define BLn (Bb*Ll)      // 192

// ---------------- scratch (static device memory; no allocations) ----------------
__device__ float g_q [M1*Dd];
__device__ float g_k [M2*Dd];
__device__ float g_v [M2*Dd];
__device__ float g_t [M1*Dd];
__device__ float g_h [M1*Dd];
__device__ float g_xn[M1*Dd];
__device__ float g_y [M1*Dd];
__device__ float g_go[(long long)BLn*Dd*Nn];        // gout fp32
__device__ __half g_bigH[(long long)M1*DF];         // y1 (fp16), then A-adj (fp16)
__device__ __half g_HbH[(long long)BLn*640*Nn];     // Hc fp16: [192][640][512]
__device__ __half g_supH[Nn*Nn];                    // support fp16

__device__ __forceinline__ uint32_t h2u(__half2 h) {
    uint32_t u;
    memcpy(&u, &h, 4);
    return u;
}

// ---------------- FP16 tensor-core GEMM (template-specialized storage) ----------------
// C = A@B (+bias)(+relu). A[M,K], B[K,N], C[M,N]; AH/BH/CH compile-time fp16 flags.
// 128x128 tile, k-step 32, 8 warps, fp32 accumulate.
// Per batch z: A += (modA? z%modA : z)*sA ; B += z*sB ; C += z*sC (element strides).
template<int AH, int BH, int CH>
__global__ void __launch_bounds__(256) hgemm_kernel(
    const void* __restrict__ Av, const void* __restrict__ Bv, void* __restrict__ Cv,
    int M, int N, int K,
    long long sA, long long sB, long long sC, int modA,
    const float* __restrict__ bias, int doRelu)
{
    __shared__ uint32_t As2[128][18];   // half2 bits [m][k/2]
    __shared__ uint32_t Bs2[128][18];   // half2 bits [n][k/2]

    int z = blockIdx.z;
    long long za = (modA > 0 ? (z % modA) : z);

    int tid  = threadIdx.x;
    int warp = tid >> 5;
    int lane = tid & 31;
    int wm = warp >> 2;
    int wn = warp & 3;
    int lr = lane >> 2;
    int lc = lane & 3;

    int brow = blockIdx.y * 128;
    int bcol = blockIdx.x * 128;

    int rA = tid >> 3;            // 0..31
    int cA = (tid & 7) * 4;       // 0..28
    int nB = tid & 127;
    int kqB = tid >> 7;           // 0..1

    float acc[4][4][4];
    #pragma unroll
    for (int i = 0; i < 4; i++)
        #pragma unroll
        for (int j = 0; j < 4; j++)
            #pragma unroll
            for (int r = 0; r < 4; r++) acc[i][j][r] = 0.f;

    for (int k0 = 0; k0 < K; k0 += 32) {
        // ---- stage A tile 128x32 ----
        if (AH) {
            const __half* Ah = (const __half*)Av + za * sA;
            #pragma unroll
            for (int u = 0; u < 4; u++) {
                int r = rA + u * 32;
                uint2 pk = *(const uint2*)(Ah + (long long)(brow + r) * K + k0 + cA);
                *(uint2*)&As2[r][cA >> 1] = pk;
            }
        } else {
            const float* Af = (const float*)Av + za * sA;
            #pragma unroll
            for (int u = 0; u < 4; u++) {
                int r = rA + u * 32;
                float4 va = *(const float4*)(Af + (long long)(brow + r) * K + k0 + cA);
                uint2 pk = make_uint2(h2u(__floats2half2_rn(va.x, va.y)),
                                      h2u(__floats2half2_rn(va.z, va.w)));
                *(uint2*)&As2[r][cA >> 1] = pk;
            }
        }
        // ---- stage B tile 32x128 (transpose during STS) ----
        if (BH) {
            const __half* Bh = (const __half*)Bv + (long long)z * sB;
            #pragma unroll
            for (int u = 0; u < 4; u++) {
                int kq = kqB + u * 2;
                int kk = k0 + kq * 4;
                const __half* bp = Bh + (long long)kk * N + bcol + nB;
                __half b0 = bp[0], b1 = bp[N], b2 = bp[2*N], b3 = bp[3*N];
                uint2 pk = make_uint2(h2u(__halves2half2(b0, b1)),
                                      h2u(__halves2half2(b2, b3)));
                *(uint2*)&Bs2[nB][kq << 1] = pk;
            }
        } else {
            const float* Bf = (const float*)Bv + (long long)z * sB;
            #pragma unroll
            for (int u = 0; u < 4; u++) {
                int kq = kqB + u * 2;
                int kk = k0 + kq * 4;
                const float* bp = Bf + (long long)kk * N + bcol + nB;
                float f0 = bp[0], f1 = bp[N], f2 = bp[2*N], f3 = bp[3*N];
                uint2 pk = make_uint2(h2u(__floats2half2_rn(f0, f1)),
                                      h2u(__floats2half2_rn(f2, f3)));
                *(uint2*)&Bs2[nB][kq << 1] = pk;
            }
        }
        __syncthreads();

        #pragma unroll
        for (int kk = 0; kk < 2; kk++) {
            int kb = kk * 8;
            uint32_t a[4][4], b[4][2];
            #pragma unroll
            for (int mf = 0; mf < 4; mf++) {
                int row = wm*64 + mf*16 + lr;
                a[mf][0] = As2[row  ][kb + lc];
                a[mf][1] = As2[row+8][kb + lc];
                a[mf][2] = As2[row  ][kb + lc + 4];
                a[mf][3] = As2[row+8][kb + lc + 4];
            }
            #pragma unroll
            for (int nf = 0; nf < 4; nf++) {
                int col = wn*32 + nf*8 + lr;
                b[nf][0] = Bs2[col][kb + lc];
                b[nf][1] = Bs2[col][kb + lc + 4];
            }
            #pragma unroll
            for (int mf = 0; mf < 4; mf++)
                #pragma unroll
                for (int nf = 0; nf < 4; nf++) {
                    asm volatile(
                        "mma.sync.aligned.m16n8k16.row.col.f32.f16.f16.f32 "
                        "{%0,%1,%2,%3}, {%4,%5,%6,%7}, {%8,%9}, {%0,%1,%2,%3};\n"
                        : "+f"(acc[mf][nf][0]), "+f"(acc[mf][nf][1]),
                          "+f"(acc[mf][nf][2]), "+f"(acc[mf][nf][3])
                        : "r"(a[mf][0]), "r"(a[mf][1]), "r"(a[mf][2]), "r"(a[mf][3]),
                          "r"(b[nf][0]), "r"(b[nf][1]));
                }
        }
        __syncthreads();
    }

    // epilogue
    #pragma unroll
    for (int mf = 0; mf < 4; mf++) {
        int row0 = brow + wm*64 + mf*16 + lr;
        #pragma unroll
        for (int nf = 0; nf < 4; nf++) {
            int col = bcol + wn*32 + nf*8 + lc*2;
            float bx = 0.f, by = 0.f;
            if (bias) { bx = bias[col]; by = bias[col+1]; }
            float v0 = acc[mf][nf][0] + bx;
            float v1 = acc[mf][nf][1] + by;
            float v2 = acc[mf][nf][2] + bx;
            float v3 = acc[mf][nf][3] + by;
            if (doRelu) {
                v0 = fmaxf(v0, 0.f); v1 = fmaxf(v1, 0.f);
                v2 = fmaxf(v2, 0.f); v3 = fmaxf(v3, 0.f);
            }
            if (CH) {
                __half* Ch = (__half*)Cv + (long long)z * sC;
                *(__half2*)(Ch + (long long)row0*N + col)     = __floats2half2_rn(v0, v1);
                *(__half2*)(Ch + (long long)(row0+8)*N + col) = __floats2half2_rn(v2, v3);
            } else {
                float* Cf = (float*)Cv + (long long)z * sC;
                *(float2*)(Cf + (long long)row0*N + col)     = make_float2(v0, v1);
                *(float2*)(Cf + (long long)(row0+8)*N + col) = make_float2(v2, v3);
            }
        }
    }
}

// ---------------- attention: one block per (b, n, h), 256 threads ----------------
#define STP 52
__global__ void __launch_bounds__(256) attn_kernel(
    const float* __restrict__ Q, const float* __restrict__ Kt, const float* __restrict__ V,
    float* __restrict__ O, int Lq, int Lk)
{
    __shared__ float Qs[48*20];
    __shared__ float Ks[96*20];
    __shared__ float Vs[96*20];
    __shared__ float St[96*STP];   // [m][l]

    int bid = blockIdx.x;
    int h = bid & 7;
    int n = (bid >> 3) & (Nn - 1);
    int b = bid >> 12;
    int tid = threadIdx.x;

    for (int i = tid; i < Lq*4; i += 256) {
        int l = i >> 2, j4 = i & 3;
        *(float4*)&Qs[l*20 + j4*4] =
            *(const float4*)(Q + (((long long)(b*Lq + l))*Nn + n)*Dd + h*HD + j4*4);
    }
    for (int i = tid; i < Lk*4; i += 256) {
        int m = i >> 2, j4 = i & 3;
        long long base = (((long long)(b*Lk + m))*Nn + n)*Dd + h*HD + j4*4;
        *(float4*)&Ks[m*20 + j4*4] = *(const float4*)(Kt + base);
        *(float4*)&Vs[m*20 + j4*4] = *(const float4*)(V + base);
    }
    __syncthreads();

    const float scale = 0.25f;  // 1/sqrt(16)
    int tlc = Lq >> 1, tmc = Lk >> 2;
    for (int t = tid; t < tlc*tmc; t += 256) {
        int tl = t / tmc, tm = t - tl*tmc;
        int l0 = tl*2, m0 = tm*4;
        const float4* q0 = (const float4*)&Qs[l0*20];
        const float4* q1 = (const float4*)&Qs[(l0+1)*20];
        float4 qa0 = q0[0], qa1 = q0[1], qa2 = q0[2], qa3 = q0[3];
        float4 qb0 = q1[0], qb1 = q1[1], qb2 = q1[2], qb3 = q1[3];
        #pragma unroll
        for (int mi = 0; mi < 4; mi++) {
            const float4* kp = (const float4*)&Ks[(m0+mi)*20];
            float4 k0 = kp[0], k1 = kp[1], k2 = kp[2], k3 = kp[3];
            float sA = 0.f, sB = 0.f;
            sA = fmaf(qa0.x,k0.x,sA); sA = fmaf(qa0.y,k0.y,sA); sA = fmaf(qa0.z,k0.z,sA); sA = fmaf(qa0.w,k0.w,sA);
            sA = fmaf(qa1.x,k1.x,sA); sA = fmaf(qa1.y,k1.y,sA); sA = fmaf(qa1.z,k1.z,sA); sA = fmaf(qa1.w,k1.w,sA);
            sA = fmaf(qa2.x,k2.x,sA); sA = fmaf(qa2.y,k2.y,sA); sA = fmaf(qa2.z,k2.z,sA); sA = fmaf(qa2.w,k2.w,sA);
            sA = fmaf(qa3.x,k3.x,sA); sA = fmaf(qa3.y,k3.y,sA); sA = fmaf(qa3.z,k3.z,sA); sA = fmaf(qa3.w,k3.w,sA);
            sB = fmaf(qb0.x,k0.x,sB); sB = fmaf(qb0.y,k0.y,sB); sB = fmaf(qb0.z,k0.z,sB); sB = fmaf(qb0.w,k0.w,sB);
            sB = fmaf(qb1.x,k1.x,sB); sB = fmaf(qb1.y,k1.y,sB); sB = fmaf(qb1.z,k1.z,sB); sB = fmaf(qb1.w,k1.w,sB);
            sB = fmaf(qb2.x,k2.x,sB); sB = fmaf(qb2.y,k2.y,sB); sB = fmaf(qb2.z,k2.z,sB); sB = fmaf(qb2.w,k2.w,sB);
            sB = fmaf(qb3.x,k3.x,sB); sB = fmaf(qb3.y,k3.y,sB); sB = fmaf(qb3.z,k3.z,sB); sB = fmaf(qb3.w,k3.w,sB);
            St[(m0+mi)*STP + l0]     = sA * scale;
            St[(m0+mi)*STP + l0 + 1] = sB * scale;
        }
    }
    __syncthreads();

    if (tid < Lq) {
        float mx = -1e30f;
        for (int m = 0; m < Lk; m++) mx = fmaxf(mx, St[m*STP + tid]);
        float sum = 0.f;
        for (int m = 0; m < Lk; m++) {
            float e = __expf(St[m*STP + tid] - mx);
            St[m*STP + tid] = e;
            sum += e;
        }
        float inv = 1.f / sum;
        for (int m = 0; m < Lk; m++) St[m*STP + tid] *= inv;
    }
    __syncthreads();

    // AV: 192 active threads (1 l, 4-col float4 each); St scalar reads broadcast
    if (tid < Lq * 4) {
        int l = tid >> 2, j4 = tid & 3;
        float4 a = make_float4(0.f, 0.f, 0.f, 0.f);
        #pragma unroll 4
        for (int m = 0; m < Lk; m++) {
            float w = St[m*STP + l];
            float4 v = *(const float4*)&Vs[m*20 + j4*4];
            a.x = fmaf(w, v.x, a.x);
            a.y = fmaf(w, v.y, a.y);
            a.z = fmaf(w, v.z, a.z);
            a.w = fmaf(w, v.w, a.w);
        }
        *(float4*)(O + (((long long)(b*Lq + l))*Nn + n)*Dd + h*HD + j4*4) = a;
    }
}

// ---------------- fused residual add + LayerNorm ----------------
__global__ void __launch_bounds__(256) ln_add_kernel(
    float* __restrict__ out, const float* __restrict__ X, const float* __restrict__ P,
    const float* __restrict__ g, const float* __restrict__ bta, int rows)
{
    int row  = (blockIdx.x * 256 + threadIdx.x) >> 5;
    int lane = threadIdx.x & 31;
    if (row >= rows) return;
    long long base = (long long)row * Dd + lane*4;
    float4 a = *(const float4*)(X + base);
    float4 p = *(const float4*)(P + base);
    float v0 = a.x+p.x, v1 = a.y+p.y, v2 = a.z+p.z, v3 = a.w+p.w;
    float s  = v0+v1+v2+v3;
    float s2 = v0*v0+v1*v1+v2*v2+v3*v3;
    #pragma unroll
    for (int o = 16; o; o >>= 1) {
        s  += __shfl_xor_sync(0xffffffffu, s,  o);
        s2 += __shfl_xor_sync(0xffffffffu, s2, o);
    }
    float mu  = s * (1.f/128.f);
    float var = s2 * (1.f/128.f) - mu*mu;
    float rs  = rsqrtf(var + 1e-5f);
    float4 gg = *(const float4*)(g   + lane*4);
    float4 bb = *(const float4*)(bta + lane*4);
    float4 o4;
    o4.x = (v0-mu)*rs*gg.x + bb.x;
    o4.y = (v1-mu)*rs*gg.y + bb.y;
    o4.z = (v2-mu)*rs*gg.z + bb.z;
    o4.w = (v3-mu)*rs*gg.w + bb.w;
    *(float4*)(out + base) = o4;
}

// ---------------- transpose data[bl] [512,128] -> fp16 g0 rows of Hc [128,512] ----------------
__global__ void transpose_g0_kernel(const float* __restrict__ in, __half* __restrict__ out)
{
    __shared__ float t[32][33];
    int bl = blockIdx.z;
    int n0 = blockIdx.x * 32;
    int c0 = blockIdx.y * 32;
    const float* ip = in  + (long long)bl * (Nn*Dd);
    __half*      op = out + (long long)bl * (640*Nn);
    #pragma unroll
    for (int j = 0; j < 32; j += 8)
        t[threadIdx.y + j][threadIdx.x] = ip[(n0 + threadIdx.y + j)*Dd + c0 + threadIdx.x];
    __syncthreads();
    #pragma unroll
    for (int j = 0; j < 32; j += 8)
        op[(c0 + threadIdx.y + j)*Nn + n0 + threadIdx.x] = __float2half(t[threadIdx.x][threadIdx.y + j]);
}

// ---------------- transpose gout[bl] [128,512] + gcn_b -> dts [512,128] ----------------
__global__ void transpose_gout_kernel(const float* __restrict__ in, const float* __restrict__ gb,
                                      float* __restrict__ out)
{
    __shared__ float t[32][33];
    int bl = blockIdx.z;
    int l  = bl % Ll;
    int n0 = blockIdx.x * 32;
    int o0 = blockIdx.y * 32;
    const float* ip = in  + (long long)bl * (Dd*Nn);
    float*       op = out + (long long)bl * (Nn*Dd);
    #pragma unroll
    for (int j = 0; j < 32; j += 8)
        t[threadIdx.y + j][threadIdx.x] = ip[(o0 + threadIdx.y + j)*Nn + n0 + threadIdx.x];
    __syncthreads();
    #pragma unroll
    for (int j = 0; j < 32; j += 8) {
        int o = o0 + threadIdx.x;
        op[(n0 + threadIdx.y + j)*Dd + o] = t[threadIdx.x][threadIdx.y + j] + gb[l*Dd + o];
    }
}

// ---------------- fp32 -> fp16 convert ----------------
__global__ void f2h_kernel(const float* __restrict__ in, __half* __restrict__ out, int n4)
{
    int i = blockIdx.x * 256 + threadIdx.x;
    if (i < n4) {
        float4 v = ((const float4*)in)[i];
        __half2 h0 = __floats2half2_rn(v.x, v.y);
        __half2 h1 = __floats2half2_rn(v.z, v.w);
        ((uint2*)out)[i] = make_uint2(h2u(h0), h2u(h1));
    }
}

// ---------------- host ----------------
template<int AH, int BH, int CH>
static inline void gemmT(const void* A, const void* B, void* C, int M, int N, int K,
                         long long sA, long long sB, long long sC, int batch, int modA,
                         const float* bias, int relu)
{
    dim3 grid(N/128, M/128, batch);
    hgemm_kernel<AH,BH,CH><<<grid, 256>>>(A, B, C, M, N, K, sA, sB, sC, modA, bias, relu);
}

extern "C" void kernel_launch(void* const* d_in, const int* in_sizes, int n_in,
                              void* d_out, int out_size)
{
    const float* x       = (const float*)d_in[0];
    const float* memory  = (const float*)d_in[1];
    const float* data    = (const float*)d_in[2];
    const float* support = (const float*)d_in[3];
    const float* Wq_s = (const float*)d_in[4];
    const float* Wk_s = (const float*)d_in[5];
    const float* Wv_s = (const float*)d_in[6];
    const float* Wo_s = (const float*)d_in[7];
    const float* Wq_c = (const float*)d_in[8];
    const float* Wk_c = (const float*)d_in[9];
    const float* Wv_c = (const float*)d_in[10];
    const float* Wo_c = (const float*)d_in[11];
    const float* W1   = (const float*)d_in[12];
    const float* b1   = (const float*)d_in[13];
    const float* W2   = (const float*)d_in[14];
    const float* b2   = (const float*)d_in[15];
    const float* W3   = (const float*)d_in[16];
    const float* b3   = (const float*)d_in[17];
    const float* gcnW = (const float*)d_in[18];
    const float* gcnB = (const float*)d_in[19];
    const float* ln1g = (const float*)d_in[20];
    const float* ln1b = (const float*)d_in[21];
    const float* ln2g = (const float*)d_in[22];
    const float* ln2b = (const float*)d_in[23];
    const float* ln3g = (const float*)d_in[24];
    const float* ln3b = (const float*)d_in[25];

    float *q, *k, *v, *t, *h, *xn, *y, *go;
    __half *bigH, *HbH, *supH;
    cudaGetSymbolAddress((void**)&q,  g_q);
    cudaGetSymbolAddress((void**)&k,  g_k);
    cudaGetSymbolAddress((void**)&v,  g_v);
    cudaGetSymbolAddress((void**)&t,  g_t);
    cudaGetSymbolAddress((void**)&h,  g_h);
    cudaGetSymbolAddress((void**)&xn, g_xn);
    cudaGetSymbolAddress((void**)&y,  g_y);
    cudaGetSymbolAddress((void**)&go, g_go);
    cudaGetSymbolAddress((void**)&bigH, g_bigH);
    cudaGetSymbolAddress((void**)&HbH, g_HbH);
    cudaGetSymbolAddress((void**)&supH, g_supH);

    float* out1 = (float*)d_out;               // LN3(xn + y)
    float* out2 = out1 + (long long)M1 * Dd;   // dts

    const int nLnBlocks = M1 / 8;

    // support -> fp16 (tiny, done up front)
    f2h_kernel<<<(Nn*Nn/4 + 255)/256, 256>>>(support, supH, Nn*Nn/4);

    // ---- self-attention ----
    gemmT<0,0,0>(x, Wq_s, q, M1, Dd, Dd, 0,0,0, 1,0, nullptr, 0);
    gemmT<0,0,0>(x, Wk_s, k, M1, Dd, Dd, 0,0,0, 1,0, nullptr, 0);
    gemmT<0,0,0>(x, Wv_s, v, M1, Dd, Dd, 0,0,0, 1,0, nullptr, 0);
    attn_kernel<<<Bb*Nn*Hh, 256>>>(q, k, v, t, Ll, Ll);
    gemmT<0,0,0>(t, Wo_s, q, M1, Dd, Dd, 0,0,0, 1,0, nullptr, 0);
    ln_add_kernel<<<nLnBlocks, 256>>>(h, x, q, ln1g, ln1b, M1);

    // ---- cross-attention ----
    gemmT<0,0,0>(h,      Wq_c, t, M1, Dd, Dd, 0,0,0, 1,0, nullptr, 0);
    gemmT<0,0,0>(memory, Wk_c, k, M2, Dd, Dd, 0,0,0, 1,0, nullptr, 0);
    gemmT<0,0,0>(memory, Wv_c, v, M2, Dd, Dd, 0,0,0, 1,0, nullptr, 0);
    attn_kernel<<<Bb*Nn*Hh, 256>>>(t, k, v, q, Ll, LP);
    gemmT<0,0,0>(q, Wo_c, t, M1, Dd, Dd, 0,0,0, 1,0, nullptr, 0);
    ln_add_kernel<<<nLnBlocks, 256>>>(xn, h, t, ln2g, ln2b, M1);

    // ---- FFN (hidden y1 kept in fp16) ----
    gemmT<0,0,1>(xn,   W1, bigH, M1, DF, Dd, 0,0,0, 1,0, b1, 1);
    gemmT<1,0,0>(bigH, W2, y,    M1, Dd, DF, 0,0,0, 1,0, b2, 0);
    ln_add_kernel<<<nLnBlocks, 256>>>(out1, xn, y, ln3g, ln3b, M1);

    // ---- dynamic adjacency A = y@W3 + b3 (fp16, reuses bigH after FFN2 consumed y1) ----
    gemmT<0,0,1>(y, W3, bigH, M1, Nn, Dd, 0,0,0, 1,0, b3, 0);

    // ---- GCN (all intermediates fp16) ----
    transpose_g0_kernel<<<dim3(16,4,BLn), dim3(32,8)>>>(data, HbH);
    gemmT<1,1,1>(HbH,          supH, HbH +  65536, 128, Nn, Nn, 327680LL, 0,        327680LL, BLn, 0, nullptr, 0);
    gemmT<1,1,1>(HbH,          bigH, HbH + 196608, 128, Nn, Nn, 327680LL, 262144LL, 327680LL, BLn, 0, nullptr, 0);
    gemmT<1,1,1>(HbH +  65536, supH, HbH + 131072, 128, Nn, Nn, 327680LL, 0,        327680LL, BLn, 0, nullptr, 0);
    gemmT<1,1,1>(HbH + 196608, bigH, HbH + 262144, 128, Nn, Nn, 327680LL, 262144LL, 327680LL, BLn, 0, nullptr, 0);
    gemmT<0,1,0>(gcnW, HbH, go, 128, Nn, 5*Dd, 81920LL, 327680LL, 65536LL, BLn, Ll, nullptr, 0);
    transpose_gout_kernel<<<dim3(16,4,BLn), dim3(32,8)>>>(go, gcnB, out2);
}

// round 10
// speedup vs baseline: 1.6856x; 1.2824x over previous
#include <cuda_runtime.h>
#include <cuda_fp16.h>
#include <cstdint>

// Shapes
#define Bb 4
#define Ll 48
#define LP 96
#define Nn 512
#define Dd 128
#define DF 512
#define Hh 8
#define HD 16

#define M1 (Bb*Ll*Nn)    // 98304
#define M2 (Bb*LP*Nn)    // 196608
#define BLn (Bb*Ll)      // 192

// ---------------- scratch (static device memory; no allocations) ----------------
__device__ float g_q [M1*Dd];
__device__ float g_t [M1*Dd];
__device__ float g_h [M1*Dd];
__device__ float g_xn[M1*Dd];
__device__ float g_y [M1*Dd];
__device__ float g_go[(long long)BLn*Dd*Nn];        // gout fp32
__device__ __half g_bigH[(long long)M1*DF];         // y1 (fp16), then A-adj (fp16)
__device__ __half g_HbH[(long long)BLn*640*Nn];     // Hc fp16: [192][640][512]
__device__ __half g_supH[Nn*Nn];                    // support fp16
__device__ __half g_qH[M1*Dd];                      // attention fp16 buffers
__device__ __half g_kH[M2*Dd];
__device__ __half g_vH[M2*Dd];
__device__ __half g_tH[M1*Dd];

__device__ __forceinline__ uint32_t h2u(__half2 h) {
    uint32_t u;
    memcpy(&u, &h, 4);
    return u;
}
__device__ __forceinline__ void cvt8(float* f, uint4 u) {
    uint32_t w[4] = {u.x, u.y, u.z, u.w};
    #pragma unroll
    for (int i = 0; i < 4; i++) {
        __half2 h;
        memcpy(&h, &w[i], 4);
        float2 g = __half22float2(h);
        f[2*i] = g.x; f[2*i+1] = g.y;
    }
}

// ---------------- FP16 tensor-core GEMM (template-specialized storage) ----------------
// C = A@B (+bias)(+relu). A[M,K], B[K,N], C[M,N]; AH/BH/CH compile-time fp16 flags.
// 128x128 tile, k-step 32, 8 warps, fp32 accumulate.
template<int AH, int BH, int CH>
__global__ void __launch_bounds__(256) hgemm_kernel(
    const void* __restrict__ Av, const void* __restrict__ Bv, void* __restrict__ Cv,
    int M, int N, int K,
    long long sA, long long sB, long long sC, int modA,
    const float* __restrict__ bias, int doRelu)
{
    __shared__ uint32_t As2[128][18];   // half2 bits [m][k/2]
    __shared__ uint32_t Bs2[128][18];   // half2 bits [n][k/2]

    int z = blockIdx.z;
    long long za = (modA > 0 ? (z % modA) : z);

    int tid  = threadIdx.x;
    int warp = tid >> 5;
    int lane = tid & 31;
    int wm = warp >> 2;
    int wn = warp & 3;
    int lr = lane >> 2;
    int lc = lane & 3;

    int brow = blockIdx.y * 128;
    int bcol = blockIdx.x * 128;

    int rA = tid >> 3;            // 0..31
    int cA = (tid & 7) * 4;       // 0..28
    int nB = tid & 127;
    int kqB = tid >> 7;           // 0..1

    float acc[4][4][4];
    #pragma unroll
    for (int i = 0; i < 4; i++)
        #pragma unroll
        for (int j = 0; j < 4; j++)
            #pragma unroll
            for (int r = 0; r < 4; r++) acc[i][j][r] = 0.f;

    for (int k0 = 0; k0 < K; k0 += 32) {
        if (AH) {
            const __half* Ah = (const __half*)Av + za * sA;
            #pragma unroll
            for (int u = 0; u < 4; u++) {
                int r = rA + u * 32;
                uint2 pk = *(const uint2*)(Ah + (long long)(brow + r) * K + k0 + cA);
                *(uint2*)&As2[r][cA >> 1] = pk;
            }
        } else {
            const float* Af = (const float*)Av + za * sA;
            #pragma unroll
            for (int u = 0; u < 4; u++) {
                int r = rA + u * 32;
                float4 va = *(const float4*)(Af + (long long)(brow + r) * K + k0 + cA);
                uint2 pk = make_uint2(h2u(__floats2half2_rn(va.x, va.y)),
                                      h2u(__floats2half2_rn(va.z, va.w)));
                *(uint2*)&As2[r][cA >> 1] = pk;
            }
        }
        if (BH) {
            const __half* Bh = (const __half*)Bv + (long long)z * sB;
            #pragma unroll
            for (int u = 0; u < 4; u++) {
                int kq = kqB + u * 2;
                int kk = k0 + kq * 4;
                const __half* bp = Bh + (long long)kk * N + bcol + nB;
                __half b0 = bp[0], b1 = bp[N], b2 = bp[2*N], b3 = bp[3*N];
                uint2 pk = make_uint2(h2u(__halves2half2(b0, b1)),
                                      h2u(__halves2half2(b2, b3)));
                *(uint2*)&Bs2[nB][kq << 1] = pk;
            }
        } else {
            const float* Bf = (const float*)Bv + (long long)z * sB;
            #pragma unroll
            for (int u = 0; u < 4; u++) {
                int kq = kqB + u * 2;
                int kk = k0 + kq * 4;
                const float* bp = Bf + (long long)kk * N + bcol + nB;
                float f0 = bp[0], f1 = bp[N], f2 = bp[2*N], f3 = bp[3*N];
                uint2 pk = make_uint2(h2u(__floats2half2_rn(f0, f1)),
                                      h2u(__floats2half2_rn(f2, f3)));
                *(uint2*)&Bs2[nB][kq << 1] = pk;
            }
        }
        __syncthreads();

        #pragma unroll
        for (int kk = 0; kk < 2; kk++) {
            int kb = kk * 8;
            uint32_t a[4][4], b[4][2];
            #pragma unroll
            for (int mf = 0; mf < 4; mf++) {
                int row = wm*64 + mf*16 + lr;
                a[mf][0] = As2[row  ][kb + lc];
                a[mf][1] = As2[row+8][kb + lc];
                a[mf][2] = As2[row  ][kb + lc + 4];
                a[mf][3] = As2[row+8][kb + lc + 4];
            }
            #pragma unroll
            for (int nf = 0; nf < 4; nf++) {
                int col = wn*32 + nf*8 + lr;
                b[nf][0] = Bs2[col][kb + lc];
                b[nf][1] = Bs2[col][kb + lc + 4];
            }
            #pragma unroll
            for (int mf = 0; mf < 4; mf++)
                #pragma unroll
                for (int nf = 0; nf < 4; nf++) {
                    asm volatile(
                        "mma.sync.aligned.m16n8k16.row.col.f32.f16.f16.f32 "
                        "{%0,%1,%2,%3}, {%4,%5,%6,%7}, {%8,%9}, {%0,%1,%2,%3};\n"
                        : "+f"(acc[mf][nf][0]), "+f"(acc[mf][nf][1]),
                          "+f"(acc[mf][nf][2]), "+f"(acc[mf][nf][3])
                        : "r"(a[mf][0]), "r"(a[mf][1]), "r"(a[mf][2]), "r"(a[mf][3]),
                          "r"(b[nf][0]), "r"(b[nf][1]));
                }
        }
        __syncthreads();
    }

    #pragma unroll
    for (int mf = 0; mf < 4; mf++) {
        int row0 = brow + wm*64 + mf*16 + lr;
        #pragma unroll
        for (int nf = 0; nf < 4; nf++) {
            int col = bcol + wn*32 + nf*8 + lc*2;
            float bx = 0.f, by = 0.f;
            if (bias) { bx = bias[col]; by = bias[col+1]; }
            float v0 = acc[mf][nf][0] + bx;
            float v1 = acc[mf][nf][1] + by;
            float v2 = acc[mf][nf][2] + bx;
            float v3 = acc[mf][nf][3] + by;
            if (doRelu) {
                v0 = fmaxf(v0, 0.f); v1 = fmaxf(v1, 0.f);
                v2 = fmaxf(v2, 0.f); v3 = fmaxf(v3, 0.f);
            }
            if (CH) {
                __half* Ch = (__half*)Cv + (long long)z * sC;
                *(__half2*)(Ch + (long long)row0*N + col)     = __floats2half2_rn(v0, v1);
                *(__half2*)(Ch + (long long)(row0+8)*N + col) = __floats2half2_rn(v2, v3);
            } else {
                float* Cf = (float*)Cv + (long long)z * sC;
                *(float2*)(Cf + (long long)row0*N + col)     = make_float2(v0, v1);
                *(float2*)(Cf + (long long)(row0+8)*N + col) = make_float2(v2, v3);
            }
        }
    }
}

// ---------------- attention: fp16 Q/K/V/O, one block per (b, n, h), 256 threads ----------------
// smem rows: 8 half2 (16 halves) used, stride 12 uint32 (48B, 16B-aligned).
#define STP 52
__global__ void __launch_bounds__(256) attn_kernel(
    const __half* __restrict__ Q, const __half* __restrict__ Kt, const __half* __restrict__ V,
    __half* __restrict__ O, int Lq, int Lk)
{
    __shared__ uint32_t Qs[48*12];
    __shared__ uint32_t Ks[96*12];
    __shared__ uint32_t Vs[96*12];
    __shared__ float St[96*STP];   // [m][l]

    int bid = blockIdx.x;
    int h = bid & 7;
    int n = (bid >> 3) & (Nn - 1);
    int b = bid >> 12;
    int tid = threadIdx.x;

    for (int i = tid; i < Lq*4; i += 256) {
        int l = i >> 2, j = i & 3;
        uint2 v = *(const uint2*)(Q + (((long long)(b*Lq + l))*Nn + n)*Dd + h*HD + j*4);
        Qs[l*12 + j*2]     = v.x;
        Qs[l*12 + j*2 + 1] = v.y;
    }
    for (int i = tid; i < Lk*4; i += 256) {
        int m = i >> 2, j = i & 3;
        long long base = (((long long)(b*Lk + m))*Nn + n)*Dd + h*HD + j*4;
        uint2 vk = *(const uint2*)(Kt + base);
        uint2 vv = *(const uint2*)(V + base);
        Ks[m*12 + j*2]     = vk.x;
        Ks[m*12 + j*2 + 1] = vk.y;
        Vs[m*12 + j*2]     = vv.x;
        Vs[m*12 + j*2 + 1] = vv.y;
    }
    __syncthreads();

    const float scale = 0.25f;  // 1/sqrt(16)
    int tlc = Lq >> 1, tmc = Lk >> 2;
    // tl varies fastest within a warp -> Q-row LDS conflict-free, K rows broadcast-ish
    for (int t = tid; t < tlc*tmc; t += 256) {
        int tl = t % tlc, tm = t / tlc;
        int l0 = tl*2, m0 = tm*4;
        float qa[16], qb[16];
        cvt8(qa,     *(const uint4*)&Qs[l0*12]);
        cvt8(qa + 8, *(const uint4*)&Qs[l0*12 + 4]);
        cvt8(qb,     *(const uint4*)&Qs[(l0+1)*12]);
        cvt8(qb + 8, *(const uint4*)&Qs[(l0+1)*12 + 4]);
        #pragma unroll
        for (int mi = 0; mi < 4; mi++) {
            float kv[16];
            cvt8(kv,     *(const uint4*)&Ks[(m0+mi)*12]);
            cvt8(kv + 8, *(const uint4*)&Ks[(m0+mi)*12 + 4]);
            float sA = 0.f, sB = 0.f;
            #pragma unroll
            for (int j = 0; j < 16; j++) {
                sA = fmaf(qa[j], kv[j], sA);
                sB = fmaf(qb[j], kv[j], sB);
            }
            St[(m0+mi)*STP + l0]     = sA * scale;
            St[(m0+mi)*STP + l0 + 1] = sB * scale;
        }
    }
    __syncthreads();

    if (tid < Lq) {
        float mx = -1e30f;
        for (int m = 0; m < Lk; m++) mx = fmaxf(mx, St[m*STP + tid]);
        float sum = 0.f;
        for (int m = 0; m < Lk; m++) {
            float e = __expf(St[m*STP + tid] - mx);
            St[m*STP + tid] = e;
            sum += e;
        }
        float inv = 1.f / sum;
        for (int m = 0; m < Lk; m++) St[m*STP + tid] *= inv;
    }
    __syncthreads();

    // AV: (l, j8) — 96 active threads, 8 output halves each via uint4 LDS of V
    if (tid < Lq * 2) {
        int l = tid >> 1, j8 = tid & 1;
        float a[8];
        #pragma unroll
        for (int j = 0; j < 8; j++) a[j] = 0.f;
        for (int m = 0; m < Lk; m++) {
            float v[8];
            cvt8(v, *(const uint4*)&Vs[m*12 + j8*4]);
            float w = St[m*STP + l];
            #pragma unroll
            for (int j = 0; j < 8; j++) a[j] = fmaf(w, v[j], a[j]);
        }
        uint4 o;
        o.x = h2u(__floats2half2_rn(a[0], a[1]));
        o.y = h2u(__floats2half2_rn(a[2], a[3]));
        o.z = h2u(__floats2half2_rn(a[4], a[5]));
        o.w = h2u(__floats2half2_rn(a[6], a[7]));
        *(uint4*)(O + (((long long)(b*Lq + l))*Nn + n)*Dd + h*HD + j8*8) = o;
    }
}

// ---------------- fused residual add + LayerNorm ----------------
__global__ void __launch_bounds__(256) ln_add_kernel(
    float* __restrict__ out, const float* __restrict__ X, const float* __restrict__ P,
    const float* __restrict__ g, const float* __restrict__ bta, int rows)
{
    int row  = (blockIdx.x * 256 + threadIdx.x) >> 5;
    int lane = threadIdx.x & 31;
    if (row >= rows) return;
    long long base = (long long)row * Dd + lane*4;
    float4 a = *(const float4*)(X + base);
    float4 p = *(const float4*)(P + base);
    float v0 = a.x+p.x, v1 = a.y+p.y, v2 = a.z+p.z, v3 = a.w+p.w;
    float s  = v0+v1+v2+v3;
    float s2 = v0*v0+v1*v1+v2*v2+v3*v3;
    #pragma unroll
    for (int o = 16; o; o >>= 1) {
        s  += __shfl_xor_sync(0xffffffffu, s,  o);
        s2 += __shfl_xor_sync(0xffffffffu, s2, o);
    }
    float mu  = s * (1.f/128.f);
    float var = s2 * (1.f/128.f) - mu*mu;
    float rs  = rsqrtf(var + 1e-5f);
    float4 gg = *(const float4*)(g   + lane*4);
    float4 bb = *(const float4*)(bta + lane*4);
    float4 o4;
    o4.x = (v0-mu)*rs*gg.x + bb.x;
    o4.y = (v1-mu)*rs*gg.y + bb.y;
    o4.z = (v2-mu)*rs*gg.z + bb.z;
    o4.w = (v3-mu)*rs*gg.w + bb.w;
    *(float4*)(out + base) = o4;
}

// ---------------- transpose data[bl] [512,128] -> fp16 g0 rows of Hc [128,512] ----------------
__global__ void transpose_g0_kernel(const float* __restrict__ in, __half* __restrict__ out)
{
    __shared__ float t[32][33];
    int bl = blockIdx.z;
    int n0 = blockIdx.x * 32;
    int c0 = blockIdx.y * 32;
    const float* ip = in  + (long long)bl * (Nn*Dd);
    __half*      op = out + (long long)bl * (640*Nn);
    #pragma unroll
    for (int j = 0; j < 32; j += 8)
        t[threadIdx.y + j][threadIdx.x] = ip[(n0 + threadIdx.y + j)*Dd + c0 + threadIdx.x];
    __syncthreads();
    #pragma unroll
    for (int j = 0; j < 32; j += 8)
        op[(c0 + threadIdx.y + j)*Nn + n0 + threadIdx.x] = __float2half(t[threadIdx.x][threadIdx.y + j]);
}

// ---------------- transpose gout[bl] [128,512] + gcn_b -> dts [512,128] ----------------
__global__ void transpose_gout_kernel(const float* __restrict__ in, const float* __restrict__ gb,
                                      float* __restrict__ out)
{
    __shared__ float t[32][33];
    int bl = blockIdx.z;
    int l  = bl % Ll;
    int n0 = blockIdx.x * 32;
    int o0 = blockIdx.y * 32;
    const float* ip = in  + (long long)bl * (Dd*Nn);
    float*       op = out + (long long)bl * (Nn*Dd);
    #pragma unroll
    for (int j = 0; j < 32; j += 8)
        t[threadIdx.y + j][threadIdx.x] = ip[(o0 + threadIdx.y + j)*Nn + n0 + threadIdx.x];
    __syncthreads();
    #pragma unroll
    for (int j = 0; j < 32; j += 8) {
        int o = o0 + threadIdx.x;
        op[(n0 + threadIdx.y + j)*Dd + o] = t[threadIdx.x][threadIdx.y + j] + gb[l*Dd + o];
    }
}

// ---------------- fp32 -> fp16 convert ----------------
__global__ void f2h_kernel(const float* __restrict__ in, __half* __restrict__ out, int n4)
{
    int i = blockIdx.x * 256 + threadIdx.x;
    if (i < n4) {
        float4 v = ((const float4*)in)[i];
        ((uint2*)out)[i] = make_uint2(h2u(__floats2half2_rn(v.x, v.y)),
                                      h2u(__floats2half2_rn(v.z, v.w)));
    }
}

// ---------------- host ----------------
template<int AH, int BH, int CH>
static inline void gemmT(const void* A, const void* B, void* C, int M, int N, int K,
                         long long sA, long long sB, long long sC, int batch, int modA,
                         const float* bias, int relu)
{
    dim3 grid(N/128, M/128, batch);
    hgemm_kernel<AH,BH,CH><<<grid, 256>>>(A, B, C, M, N, K, sA, sB, sC, modA, bias, relu);
}

extern "C" void kernel_launch(void* const* d_in, const int* in_sizes, int n_in,
                              void* d_out, int out_size)
{
    const float* x       = (const float*)d_in[0];
    const float* memory  = (const float*)d_in[1];
    const float* data    = (const float*)d_in[2];
    const float* support = (const float*)d_in[3];
    const float* Wq_s = (const float*)d_in[4];
    const float* Wk_s = (const float*)d_in[5];
    const float* Wv_s = (const float*)d_in[6];
    const float* Wo_s = (const float*)d_in[7];
    const float* Wq_c = (const float*)d_in[8];
    const float* Wk_c = (const float*)d_in[9];
    const float* Wv_c = (const float*)d_in[10];
    const float* Wo_c = (const float*)d_in[11];
    const float* W1   = (const float*)d_in[12];
    const float* b1   = (const float*)d_in[13];
    const float* W2   = (const float*)d_in[14];
    const float* b2   = (const float*)d_in[15];
    const float* W3   = (const float*)d_in[16];
    const float* b3   = (const float*)d_in[17];
    const float* gcnW = (const float*)d_in[18];
    const float* gcnB = (const float*)d_in[19];
    const float* ln1g = (const float*)d_in[20];
    const float* ln1b = (const float*)d_in[21];
    const float* ln2g = (const float*)d_in[22];
    const float* ln2b = (const float*)d_in[23];
    const float* ln3g = (const float*)d_in[24];
    const float* ln3b = (const float*)d_in[25];

    float *q, *t, *h, *xn, *y, *go;
    __half *bigH, *HbH, *supH, *qH, *kH, *vH, *tH;
    cudaGetSymbolAddress((void**)&q,  g_q);
    cudaGetSymbolAddress((void**)&t,  g_t);
    cudaGetSymbolAddress((void**)&h,  g_h);
    cudaGetSymbolAddress((void**)&xn, g_xn);
    cudaGetSymbolAddress((void**)&y,  g_y);
    cudaGetSymbolAddress((void**)&go, g_go);
    cudaGetSymbolAddress((void**)&bigH, g_bigH);
    cudaGetSymbolAddress((void**)&HbH, g_HbH);
    cudaGetSymbolAddress((void**)&supH, g_supH);
    cudaGetSymbolAddress((void**)&qH, g_qH);
    cudaGetSymbolAddress((void**)&kH, g_kH);
    cudaGetSymbolAddress((void**)&vH, g_vH);
    cudaGetSymbolAddress((void**)&tH, g_tH);

    float* out1 = (float*)d_out;               // LN3(xn + y)
    float* out2 = out1 + (long long)M1 * Dd;   // dts

    const int nLnBlocks = M1 / 8;

    // support -> fp16 (tiny, done up front)
    f2h_kernel<<<(Nn*Nn/4 + 255)/256, 256>>>(support, supH, Nn*Nn/4);

    // ---- self-attention (fp16 Q/K/V/O) ----
    gemmT<0,0,1>(x, Wq_s, qH, M1, Dd, Dd, 0,0,0, 1,0, nullptr, 0);
    gemmT<0,0,1>(x, Wk_s, kH, M1, Dd, Dd, 0,0,0, 1,0, nullptr, 0);
    gemmT<0,0,1>(x, Wv_s, vH, M1, Dd, Dd, 0,0,0, 1,0, nullptr, 0);
    attn_kernel<<<Bb*Nn*Hh, 256>>>(qH, kH, vH, tH, Ll, Ll);
    gemmT<1,0,0>(tH, Wo_s, q, M1, Dd, Dd, 0,0,0, 1,0, nullptr, 0);
    ln_add_kernel<<<nLnBlocks, 256>>>(h, x, q, ln1g, ln1b, M1);

    // ---- cross-attention ----
    gemmT<0,0,1>(h,      Wq_c, tH, M1, Dd, Dd, 0,0,0, 1,0, nullptr, 0);
    gemmT<0,0,1>(memory, Wk_c, kH, M2, Dd, Dd, 0,0,0, 1,0, nullptr, 0);
    gemmT<0,0,1>(memory, Wv_c, vH, M2, Dd, Dd, 0,0,0, 1,0, nullptr, 0);
    attn_kernel<<<Bb*Nn*Hh, 256>>>(tH, kH, vH, qH, Ll, LP);
    gemmT<1,0,0>(qH, Wo_c, t, M1, Dd, Dd, 0,0,0, 1,0, nullptr, 0);
    ln_add_kernel<<<nLnBlocks, 256>>>(xn, h, t, ln2g, ln2b, M1);

    // ---- FFN (hidden y1 kept in fp16) ----
    gemmT<0,0,1>(xn,   W1, bigH, M1, DF, Dd, 0,0,0, 1,0, b1, 1);
    gemmT<1,0,0>(bigH, W2, y,    M1, Dd, DF, 0,0,0, 1,0, b2, 0);
    ln_add_kernel<<<nLnBlocks, 256>>>(out1, xn, y, ln3g, ln3b, M1);

    // ---- dynamic adjacency A = y@W3 + b3 (fp16) ----
    gemmT<0,0,1>(y, W3, bigH, M1, Nn, Dd, 0,0,0, 1,0, b3, 0);

    // ---- GCN (all intermediates fp16) ----
    transpose_g0_kernel<<<dim3(16,4,BLn), dim3(32,8)>>>(data, HbH);
    gemmT<1,1,1>(HbH,          supH, HbH +  65536, 128, Nn, Nn, 327680LL, 0,        327680LL, BLn, 0, nullptr, 0);
    gemmT<1,1,1>(HbH,          bigH, HbH + 196608, 128, Nn, Nn, 327680LL, 262144LL, 327680LL, BLn, 0, nullptr, 0);
    gemmT<1,1,1>(HbH +  65536, supH, HbH + 131072, 128, Nn, Nn, 327680LL, 0,        327680LL, BLn, 0, nullptr, 0);
    gemmT<1,1,1>(HbH + 196608, bigH, HbH + 262144, 128, Nn, Nn, 327680LL, 262144LL, 327680LL, BLn, 0, nullptr, 0);
    gemmT<0,1,0>(gcnW, HbH, go, 128, Nn, 5*Dd, 81920LL, 327680LL, 65536LL, BLn, Ll, nullptr, 0);
    transpose_gout_kernel<<<dim3(16,4,BLn), dim3(32,8)>>>(go, gcnB, out2);
}

// round 11
// speedup vs baseline: 2.3117x; 1.3715x over previous
#include <cuda_runtime.h>
#include <cuda_fp16.h>
#include <cstdint>

// Shapes
#define Bb 4
#define Ll 48
#define LP 96
#define Nn 512
#define Dd 128
#define DF 512
#define Hh 8
#define HD 16

#define M1 (Bb*Ll*Nn)    // 98304
#define M2 (Bb*LP*Nn)    // 196608
#define BLn (Bb*Ll)      // 192

// ---------------- scratch (static device memory; no allocations) ----------------
__device__ __align__(16) float g_q [M1*Dd];
__device__ __align__(16) float g_t [M1*Dd];
__device__ __align__(16) float g_h [M1*Dd];
__device__ __align__(16) float g_xn[M1*Dd];
__device__ __align__(16) float g_y [M1*Dd];
__device__ __align__(16) float g_go[(long long)BLn*Dd*Nn];
__device__ __align__(16) __half g_bigH[(long long)M1*DF];       // y1, then A-adj
__device__ __align__(16) __half g_HbH[(long long)BLn*640*Nn];   // Hc fp16
__device__ __align__(16) __half g_xH [M1*Dd];
__device__ __align__(16) __half g_memH[M2*Dd];
__device__ __align__(16) __half g_qH[M1*Dd];
__device__ __align__(16) __half g_kH[M2*Dd];   // also xnH
__device__ __align__(16) __half g_vH[M2*Dd];
__device__ __align__(16) __half g_tH[M1*Dd];   // also hH
__device__ __align__(16) __half g_wH[4521984]; // all weights fp16

// g_wH element offsets
#define W_QS 0
#define W_KS 16384
#define W_VS 32768
#define W_OS 49152
#define W_QC 65536
#define W_KC 81920
#define W_VC 98304
#define W_OC 114688
#define W_W1 131072
#define W_W2 196608
#define W_W3 262144
#define W_GW 327680
#define W_SUP 4259840

__device__ __forceinline__ uint32_t h2u(__half2 h) {
    uint32_t u; memcpy(&u, &h, 4); return u;
}
__device__ __forceinline__ void cvt8(float* f, uint4 u) {
    uint32_t w[4] = {u.x, u.y, u.z, u.w};
    #pragma unroll
    for (int i = 0; i < 4; i++) {
        __half2 h; memcpy(&h, &w[i], 4);
        float2 g = __half22float2(h);
        f[2*i] = g.x; f[2*i+1] = g.y;
    }
}
__device__ __forceinline__ uint32_t s2u(const void* p) {
    return (uint32_t)__cvta_generic_to_shared(p);
}
#define CPA16(dst, src) asm volatile("cp.async.cg.shared.global [%0], [%1], 16;\n" :: "r"(dst), "l"(src))
#define CPCOMMIT()      asm volatile("cp.async.commit_group;\n" ::: "memory")

// ---------------- cp.async + ldmatrix fp16 GEMM ----------------
// C = A@B (+bias)(+relu). A[M,K] fp16, B[K,N] fp16. CH: 0 fp32 C, 1 fp16 C, 2 both.
// 128x128 tile, k-chunk 64, double-buffered cp.async, ldmatrix fragments.
// Per batch z: A += (modA? z%modA : z)*sA ; B += z*sB ; C += z*sC (elements).
template<int CH>
__global__ void __launch_bounds__(256, 2) hgemm_kernel(
    const __half* __restrict__ A, const __half* __restrict__ B,
    void* __restrict__ Cv, __half* __restrict__ C2,
    int M, int N, int K,
    long long sA, long long sB, long long sC, int modA,
    const float* __restrict__ bias, int doRelu)
{
    extern __shared__ char smem[];
    uint32_t sb = s2u(smem);   // layout: [buf0: A 16K | B 16K][buf1: A 16K | B 16K]

    int z = blockIdx.z;
    long long za = (modA > 0 ? (z % modA) : z);
    const __half* Ag = A + za * sA + (long long)blockIdx.y * 128 * K;
    const __half* Bg = B + (long long)z * sB;

    int tid = threadIdx.x;
    int warp = tid >> 5, lane = tid & 31;
    int wm = warp >> 2, wn = warp & 3;
    int lr = lane >> 2, lc = lane & 3;
    int brow = blockIdx.y * 128, bcol = blockIdx.x * 128;

    int aRowL = (lane & 7) + ((lane >> 3) & 1) * 8;  // ldmatrix A row-in-tile
    int aKcL  = lane >> 4;                           // ldmatrix A k-chunk sel
    int bKL   = (lane & 7) + ((lane >> 3) & 1) * 8;  // ldmatrix B k-in-16
    int bNcL  = lane >> 4;                           // ldmatrix B n-chunk sel

    float acc[4][4][4];
    #pragma unroll
    for (int i = 0; i < 4; i++)
        #pragma unroll
        for (int j = 0; j < 4; j++)
            #pragma unroll
            for (int r = 0; r < 4; r++) acc[i][j][r] = 0.f;

    int nC = K >> 6;

    auto issue = [&](int ct, int bo) {
        uint32_t abase = sb + bo;
        const __half* ap = Ag + ct * 64;
        #pragma unroll
        for (int u = 0; u < 4; u++) {
            int r = u*32 + (tid >> 3);
            int cc = tid & 7;
            uint32_t dst = abase + r*128 + ((cc ^ (r & 7)) << 4);
            CPA16(dst, ap + (long long)r * K + cc*8);
        }
        uint32_t bbase = abase + 16384;
        const __half* bp = Bg + (long long)(ct*64) * N + bcol;
        #pragma unroll
        for (int u = 0; u < 4; u++) {
            int k = u*16 + (tid >> 4);
            int cc = tid & 15;
            uint32_t dst = bbase + k*256 + (((cc & 8) | ((cc & 7) ^ (k & 7))) << 4);
            CPA16(dst, bp + (long long)k * N + cc*8);
        }
        CPCOMMIT();
    };

    auto compute = [&](int bo) {
        uint32_t abase = sb + bo;
        uint32_t bbase = abase + 16384;
        #pragma unroll
        for (int kk = 0; kk < 4; kk++) {
            uint32_t af[4][4];
            #pragma unroll
            for (int mf = 0; mf < 4; mf++) {
                int row = wm*64 + mf*16 + aRowL;
                int kc = kk*2 + aKcL;
                uint32_t ad = abase + row*128 + ((kc ^ (row & 7)) << 4);
                asm volatile("ldmatrix.sync.aligned.m8n8.x4.shared.b16 {%0,%1,%2,%3}, [%4];\n"
                    : "=r"(af[mf][0]), "=r"(af[mf][1]), "=r"(af[mf][2]), "=r"(af[mf][3]) : "r"(ad));
            }
            uint32_t bf[4][2];
            #pragma unroll
            for (int np = 0; np < 2; np++) {
                int k = kk*16 + bKL;
                int nc = wn*4 + np*2 + bNcL;
                uint32_t bd = bbase + k*256 + (((nc & 8) | ((nc & 7) ^ (k & 7))) << 4);
                asm volatile("ldmatrix.sync.aligned.m8n8.x4.trans.shared.b16 {%0,%1,%2,%3}, [%4];\n"
                    : "=r"(bf[2*np][0]), "=r"(bf[2*np][1]), "=r"(bf[2*np+1][0]), "=r"(bf[2*np+1][1]) : "r"(bd));
            }
            #pragma unroll
            for (int mf = 0; mf < 4; mf++)
                #pragma unroll
                for (int nf = 0; nf < 4; nf++) {
                    asm volatile(
                        "mma.sync.aligned.m16n8k16.row.col.f32.f16.f16.f32 "
                        "{%0,%1,%2,%3}, {%4,%5,%6,%7}, {%8,%9}, {%0,%1,%2,%3};\n"
                        : "+f"(acc[mf][nf][0]), "+f"(acc[mf][nf][1]),
                          "+f"(acc[mf][nf][2]), "+f"(acc[mf][nf][3])
                        : "r"(af[mf][0]), "r"(af[mf][1]), "r"(af[mf][2]), "r"(af[mf][3]),
                          "r"(bf[nf][0]), "r"(bf[nf][1]));
                }
        }
    };

    issue(0, 0);
    int bo = 0;
    for (int c = 0; c < nC; c++) {
        if (c + 1 < nC) {
            issue(c + 1, bo ^ 32768);
            asm volatile("cp.async.wait_group 1;\n" ::: "memory");
        } else {
            asm volatile("cp.async.wait_group 0;\n" ::: "memory");
        }
        __syncthreads();
        compute(bo);
        __syncthreads();
        bo ^= 32768;
    }

    // epilogue
    #pragma unroll
    for (int mf = 0; mf < 4; mf++) {
        int row0 = brow + wm*64 + mf*16 + lr;
        #pragma unroll
        for (int nf = 0; nf < 4; nf++) {
            int col = bcol + wn*32 + nf*8 + lc*2;
            float bx = 0.f, by = 0.f;
            if (bias) { bx = bias[col]; by = bias[col+1]; }
            float v0 = acc[mf][nf][0] + bx;
            float v1 = acc[mf][nf][1] + by;
            float v2 = acc[mf][nf][2] + bx;
            float v3 = acc[mf][nf][3] + by;
            if (doRelu) {
                v0 = fmaxf(v0, 0.f); v1 = fmaxf(v1, 0.f);
                v2 = fmaxf(v2, 0.f); v3 = fmaxf(v3, 0.f);
            }
            if (CH == 0 || CH == 2) {
                float* Cf = (float*)Cv + (long long)z * sC;
                *(float2*)(Cf + (long long)row0*N + col)     = make_float2(v0, v1);
                *(float2*)(Cf + (long long)(row0+8)*N + col) = make_float2(v2, v3);
            }
            if (CH == 1) {
                __half* Ch = (__half*)Cv + (long long)z * sC;
                *(__half2*)(Ch + (long long)row0*N + col)     = __floats2half2_rn(v0, v1);
                *(__half2*)(Ch + (long long)(row0+8)*N + col) = __floats2half2_rn(v2, v3);
            }
            if (CH == 2) {
                *(__half2*)(C2 + (long long)row0*N + col)     = __floats2half2_rn(v0, v1);
                *(__half2*)(C2 + (long long)(row0+8)*N + col) = __floats2half2_rn(v2, v3);
            }
        }
    }
}

// ---------------- attention: fp16 Q/K/V/O (R10 proven) ----------------
#define STP 52
__global__ void __launch_bounds__(256) attn_kernel(
    const __half* __restrict__ Q, const __half* __restrict__ Kt, const __half* __restrict__ V,
    __half* __restrict__ O, int Lq, int Lk)
{
    __shared__ uint32_t Qs[48*12];
    __shared__ uint32_t Ks[96*12];
    __shared__ uint32_t Vs[96*12];
    __shared__ float St[96*STP];

    int bid = blockIdx.x;
    int h = bid & 7;
    int n = (bid >> 3) & (Nn - 1);
    int b = bid >> 12;
    int tid = threadIdx.x;

    for (int i = tid; i < Lq*4; i += 256) {
        int l = i >> 2, j = i & 3;
        uint2 v = *(const uint2*)(Q + (((long long)(b*Lq + l))*Nn + n)*Dd + h*HD + j*4);
        Qs[l*12 + j*2]     = v.x;
        Qs[l*12 + j*2 + 1] = v.y;
    }
    for (int i = tid; i < Lk*4; i += 256) {
        int m = i >> 2, j = i & 3;
        long long base = (((long long)(b*Lk + m))*Nn + n)*Dd + h*HD + j*4;
        uint2 vk = *(const uint2*)(Kt + base);
        uint2 vv = *(const uint2*)(V + base);
        Ks[m*12 + j*2]     = vk.x;
        Ks[m*12 + j*2 + 1] = vk.y;
        Vs[m*12 + j*2]     = vv.x;
        Vs[m*12 + j*2 + 1] = vv.y;
    }
    __syncthreads();

    const float scale = 0.25f;
    int tlc = Lq >> 1, tmc = Lk >> 2;
    for (int t = tid; t < tlc*tmc; t += 256) {
        int tl = t % tlc, tm = t / tlc;
        int l0 = tl*2, m0 = tm*4;
        float qa[16], qb[16];
        cvt8(qa,     *(const uint4*)&Qs[l0*12]);
        cvt8(qa + 8, *(const uint4*)&Qs[l0*12 + 4]);
        cvt8(qb,     *(const uint4*)&Qs[(l0+1)*12]);
        cvt8(qb + 8, *(const uint4*)&Qs[(l0+1)*12 + 4]);
        #pragma unroll
        for (int mi = 0; mi < 4; mi++) {
            float kv[16];
            cvt8(kv,     *(const uint4*)&Ks[(m0+mi)*12]);
            cvt8(kv + 8, *(const uint4*)&Ks[(m0+mi)*12 + 4]);
            float sA = 0.f, sB = 0.f;
            #pragma unroll
            for (int j = 0; j < 16; j++) {
                sA = fmaf(qa[j], kv[j], sA);
                sB = fmaf(qb[j], kv[j], sB);
            }
            St[(m0+mi)*STP + l0]     = sA * scale;
            St[(m0+mi)*STP + l0 + 1] = sB * scale;
        }
    }
    __syncthreads();

    if (tid < Lq) {
        float mx = -1e30f;
        for (int m = 0; m < Lk; m++) mx = fmaxf(mx, St[m*STP + tid]);
        float sum = 0.f;
        for (int m = 0; m < Lk; m++) {
            float e = __expf(St[m*STP + tid] - mx);
            St[m*STP + tid] = e;
            sum += e;
        }
        float inv = 1.f / sum;
        for (int m = 0; m < Lk; m++) St[m*STP + tid] *= inv;
    }
    __syncthreads();

    if (tid < Lq * 2) {
        int l = tid >> 1, j8 = tid & 1;
        float a[8];
        #pragma unroll
        for (int j = 0; j < 8; j++) a[j] = 0.f;
        for (int m = 0; m < Lk; m++) {
            float v[8];
            cvt8(v, *(const uint4*)&Vs[m*12 + j8*4]);
            float w = St[m*STP + l];
            #pragma unroll
            for (int j = 0; j < 8; j++) a[j] = fmaf(w, v[j], a[j]);
        }
        uint4 o;
        o.x = h2u(__floats2half2_rn(a[0], a[1]));
        o.y = h2u(__floats2half2_rn(a[2], a[3]));
        o.z = h2u(__floats2half2_rn(a[4], a[5]));
        o.w = h2u(__floats2half2_rn(a[6], a[7]));
        *(uint4*)(O + (((long long)(b*Lq + l))*Nn + n)*Dd + h*HD + j8*8) = o;
    }
}

// ---------------- residual add + LayerNorm (optional fp16 dual output) ----------------
template<int DUAL>
__global__ void __launch_bounds__(256) ln_add_kernel(
    float* __restrict__ out, __half* __restrict__ outH,
    const float* __restrict__ X, const float* __restrict__ P,
    const float* __restrict__ g, const float* __restrict__ bta, int rows)
{
    int row  = (blockIdx.x * 256 + threadIdx.x) >> 5;
    int lane = threadIdx.x & 31;
    if (row >= rows) return;
    long long base = (long long)row * Dd + lane*4;
    float4 a = *(const float4*)(X + base);
    float4 p = *(const float4*)(P + base);
    float v0 = a.x+p.x, v1 = a.y+p.y, v2 = a.z+p.z, v3 = a.w+p.w;
    float s  = v0+v1+v2+v3;
    float s2 = v0*v0+v1*v1+v2*v2+v3*v3;
    #pragma unroll
    for (int o = 16; o; o >>= 1) {
        s  += __shfl_xor_sync(0xffffffffu, s,  o);
        s2 += __shfl_xor_sync(0xffffffffu, s2, o);
    }
    float mu  = s * (1.f/128.f);
    float var = s2 * (1.f/128.f) - mu*mu;
    float rs  = rsqrtf(var + 1e-5f);
    float4 gg = *(const float4*)(g   + lane*4);
    float4 bb = *(const float4*)(bta + lane*4);
    float4 o4;
    o4.x = (v0-mu)*rs*gg.x + bb.x;
    o4.y = (v1-mu)*rs*gg.y + bb.y;
    o4.z = (v2-mu)*rs*gg.z + bb.z;
    o4.w = (v3-mu)*rs*gg.w + bb.w;
    *(float4*)(out + base) = o4;
    if (DUAL) {
        uint2 hp = make_uint2(h2u(__floats2half2_rn(o4.x, o4.y)),
                              h2u(__floats2half2_rn(o4.z, o4.w)));
        *(uint2*)(outH + base) = hp;
    }
}

// ---------------- transpose data[bl] [512,128] -> fp16 g0 rows of Hc [128,512] ----------------
__global__ void transpose_g0_kernel(const float* __restrict__ in, __half* __restrict__ out)
{
    __shared__ float t[32][33];
    int bl = blockIdx.z;
    int n0 = blockIdx.x * 32;
    int c0 = blockIdx.y * 32;
    const float* ip = in  + (long long)bl * (Nn*Dd);
    __half*      op = out + (long long)bl * (640*Nn);
    #pragma unroll
    for (int j = 0; j < 32; j += 8)
        t[threadIdx.y + j][threadIdx.x] = ip[(n0 + threadIdx.y + j)*Dd + c0 + threadIdx.x];
    __syncthreads();
    #pragma unroll
    for (int j = 0; j < 32; j += 8)
        op[(c0 + threadIdx.y + j)*Nn + n0 + threadIdx.x] = __float2half(t[threadIdx.x][threadIdx.y + j]);
}

// ---------------- transpose gout[bl] [128,512] + gcn_b -> dts [512,128] ----------------
__global__ void transpose_gout_kernel(const float* __restrict__ in, const float* __restrict__ gb,
                                      float* __restrict__ out)
{
    __shared__ float t[32][33];
    int bl = blockIdx.z;
    int l  = bl % Ll;
    int n0 = blockIdx.x * 32;
    int o0 = blockIdx.y * 32;
    const float* ip = in  + (long long)bl * (Dd*Nn);
    float*       op = out + (long long)bl * (Nn*Dd);
    #pragma unroll
    for (int j = 0; j < 32; j += 8)
        t[threadIdx.y + j][threadIdx.x] = ip[(o0 + threadIdx.y + j)*Nn + n0 + threadIdx.x];
    __syncthreads();
    #pragma unroll
    for (int j = 0; j < 32; j += 8) {
        int o = o0 + threadIdx.x;
        op[(n0 + threadIdx.y + j)*Dd + o] = t[threadIdx.x][threadIdx.y + j] + gb[l*Dd + o];
    }
}

// ---------------- fp32 -> fp16 convert ----------------
__global__ void f2h_kernel(const float* __restrict__ in, __half* __restrict__ out, int n4)
{
    int i = blockIdx.x * 256 + threadIdx.x;
    if (i < n4) {
        float4 v = ((const float4*)in)[i];
        ((uint2*)out)[i] = make_uint2(h2u(__floats2half2_rn(v.x, v.y)),
                                      h2u(__floats2half2_rn(v.z, v.w)));
    }
}

// ---------------- host ----------------
#define GSMEM 65536

template<int CH>
static inline void gemmT(const __half* A, const __half* B, void* C, __half* C2,
                         int M, int N, int K,
                         long long sA, long long sB, long long sC, int batch, int modA,
                         const float* bias, int relu)
{
    dim3 grid(N/128, M/128, batch);
    hgemm_kernel<CH><<<grid, 256, GSMEM>>>(A, B, C, C2, M, N, K, sA, sB, sC, modA, bias, relu);
}

static inline void f2h(const float* in, __half* out, long long n)
{
    int n4 = (int)(n / 4);
    f2h_kernel<<<(n4 + 255)/256, 256>>>(in, out, n4);
}

extern "C" void kernel_launch(void* const* d_in, const int* in_sizes, int n_in,
                              void* d_out, int out_size)
{
    const float* x       = (const float*)d_in[0];
    const float* memory  = (const float*)d_in[1];
    const float* data    = (const float*)d_in[2];
    const float* support = (const float*)d_in[3];
    const float* Ws[8]   = { (const float*)d_in[4], (const float*)d_in[5],
                             (const float*)d_in[6], (const float*)d_in[7],
                             (const float*)d_in[8], (const float*)d_in[9],
                             (const float*)d_in[10], (const float*)d_in[11] };
    const float* W1   = (const float*)d_in[12];
    const float* b1   = (const float*)d_in[13];
    const float* W2   = (const float*)d_in[14];
    const float* b2   = (const float*)d_in[15];
    const float* W3   = (const float*)d_in[16];
    const float* b3   = (const float*)d_in[17];
    const float* gcnW = (const float*)d_in[18];
    const float* gcnB = (const float*)d_in[19];
    const float* ln1g = (const float*)d_in[20];
    const float* ln1b = (const float*)d_in[21];
    const float* ln2g = (const float*)d_in[22];
    const float* ln2b = (const float*)d_in[23];
    const float* ln3g = (const float*)d_in[24];
    const float* ln3b = (const float*)d_in[25];

    float *q, *t, *h, *xn, *y, *go;
    __half *bigH, *HbH, *xH, *memH, *qH, *kH, *vH, *tH, *wH;
    cudaGetSymbolAddress((void**)&q,  g_q);
    cudaGetSymbolAddress((void**)&t,  g_t);
    cudaGetSymbolAddress((void**)&h,  g_h);
    cudaGetSymbolAddress((void**)&xn, g_xn);
    cudaGetSymbolAddress((void**)&y,  g_y);
    cudaGetSymbolAddress((void**)&go, g_go);
    cudaGetSymbolAddress((void**)&bigH, g_bigH);
    cudaGetSymbolAddress((void**)&HbH, g_HbH);
    cudaGetSymbolAddress((void**)&xH, g_xH);
    cudaGetSymbolAddress((void**)&memH, g_memH);
    cudaGetSymbolAddress((void**)&qH, g_qH);
    cudaGetSymbolAddress((void**)&kH, g_kH);
    cudaGetSymbolAddress((void**)&vH, g_vH);
    cudaGetSymbolAddress((void**)&tH, g_tH);
    cudaGetSymbolAddress((void**)&wH, g_wH);

    cudaFuncSetAttribute(hgemm_kernel<0>, cudaFuncAttributeMaxDynamicSharedMemorySize, GSMEM);
    cudaFuncSetAttribute(hgemm_kernel<1>, cudaFuncAttributeMaxDynamicSharedMemorySize, GSMEM);
    cudaFuncSetAttribute(hgemm_kernel<2>, cudaFuncAttributeMaxDynamicSharedMemorySize, GSMEM);

    float* out1 = (float*)d_out;               // LN3(xn + y)
    float* out2 = out1 + (long long)M1 * Dd;   // dts

    const int nLn = M1 / 8;

    // ---- fp16 conversions (inputs + weights; identical rn rounding to prior STS path) ----
    f2h(x, xH, (long long)M1*Dd);
    f2h(memory, memH, (long long)M2*Dd);
    int wOff[8] = { W_QS, W_KS, W_VS, W_OS, W_QC, W_KC, W_VC, W_OC };
    for (int i = 0; i < 8; i++) f2h(Ws[i], wH + wOff[i], 16384);
    f2h(W1, wH + W_W1, 65536);
    f2h(W2, wH + W_W2, 65536);
    f2h(W3, wH + W_W3, 65536);
    f2h(gcnW, wH + W_GW, (long long)Ll*Dd*640);
    f2h(support, wH + W_SUP, Nn*Nn);

    // ---- self-attention ----
    gemmT<1>(xH, wH+W_QS, qH, 0, M1,128,128, 0,0,0, 1,0, nullptr, 0);
    gemmT<1>(xH, wH+W_KS, kH, 0, M1,128,128, 0,0,0, 1,0, nullptr, 0);
    gemmT<1>(xH, wH+W_VS, vH, 0, M1,128,128, 0,0,0, 1,0, nullptr, 0);
    attn_kernel<<<Bb*Nn*Hh, 256>>>(qH, kH, vH, tH, Ll, Ll);
    gemmT<0>(tH, wH+W_OS, q, 0, M1,128,128, 0,0,0, 1,0, nullptr, 0);
    ln_add_kernel<1><<<nLn, 256>>>(h, tH, x, q, ln1g, ln1b, M1);    // hH = tH

    // ---- cross-attention ----
    gemmT<1>(tH,   wH+W_QC, qH, 0, M1,128,128, 0,0,0, 1,0, nullptr, 0);
    gemmT<1>(memH, wH+W_KC, kH, 0, M2,128,128, 0,0,0, 1,0, nullptr, 0);
    gemmT<1>(memH, wH+W_VC, vH, 0, M2,128,128, 0,0,0, 1,0, nullptr, 0);
    attn_kernel<<<Bb*Nn*Hh, 256>>>(qH, kH, vH, tH, Ll, LP);
    gemmT<0>(tH, wH+W_OC, t, 0, M1,128,128, 0,0,0, 1,0, nullptr, 0);
    ln_add_kernel<1><<<nLn, 256>>>(xn, kH, h, t, ln2g, ln2b, M1);   // xnH = kH

    // ---- FFN (y1 fp16; y dual fp32+fp16) ----
    gemmT<1>(kH,   wH+W_W1, bigH, 0,  M1,512,128, 0,0,0, 1,0, b1, 1);
    gemmT<2>(bigH, wH+W_W2, y,    qH, M1,128,512, 0,0,0, 1,0, b2, 0);   // yH = qH
    ln_add_kernel<0><<<nLn, 256>>>(out1, 0, xn, y, ln3g, ln3b, M1);

    // ---- dynamic adjacency A = y@W3 + b3 (fp16) ----
    gemmT<1>(qH, wH+W_W3, bigH, 0, M1,512,128, 0,0,0, 1,0, b3, 0);

    // ---- GCN (all fp16) ----
    transpose_g0_kernel<<<dim3(16,4,BLn), dim3(32,8)>>>(data, HbH);
    gemmT<1>(HbH,          wH+W_SUP, HbH +  65536, 0, 128,512,512, 327680,0,      327680, BLn,0, nullptr, 0);
    gemmT<1>(HbH,          bigH,     HbH + 196608, 0, 128,512,512, 327680,262144, 327680, BLn,0, nullptr, 0);
    gemmT<1>(HbH +  65536, wH+W_SUP, HbH + 131072, 0, 128,512,512, 327680,0,      327680, BLn,0, nullptr, 0);
    gemmT<1>(HbH + 196608, bigH,     HbH + 262144, 0, 128,512,512, 327680,262144, 327680, BLn,0, nullptr, 0);
    gemmT<0>(wH+W_GW, HbH, go, 0, 128,512,640, 81920,327680,65536, BLn,Ll, nullptr, 0);
    transpose_gout_kernel<<<dim3(16,4,BLn), dim3(32,8)>>>(go, gcnB, out2);
}

// round 12
// speedup vs baseline: 2.3214x; 1.0042x over previous
#include <cuda_runtime.h>
#include <cuda_fp16.h>
#include <cstdint>

// Shapes
#define Bb 4
#define Ll 48
#define LP 96
#define Nn 512
#define Dd 128
#define DF 512
#define Hh 8
#define HD 16

#define M1 (Bb*Ll*Nn)    // 98304
#define M2 (Bb*LP*Nn)    // 196608
#define BLn (Bb*Ll)      // 192

// ---------------- scratch (static device memory; no allocations) ----------------
__device__ __align__(16) float g_q [M1*Dd];
__device__ __align__(16) float g_t [M1*Dd];
__device__ __align__(16) float g_h [M1*Dd];
__device__ __align__(16) float g_xn[M1*Dd];
__device__ __align__(16) float g_y [M1*Dd];
__device__ __align__(16) __half g_bigH[(long long)M1*DF];       // y1, then A-adj
__device__ __align__(16) __half g_HbH[(long long)BLn*640*Nn];   // Hc fp16
__device__ __align__(16) __half g_xH [M1*Dd];
__device__ __align__(16) __half g_memH[M2*Dd];
__device__ __align__(16) __half g_qkvH[3*M1*Dd];                // self QKV
__device__ __align__(16) __half g_kvH[2*M2*Dd];                 // cross KV
__device__ __align__(16) __half g_qH[M1*Dd];
__device__ __align__(16) __half g_tH[M1*Dd];   // also hH
__device__ __align__(16) __half g_xnH[M1*Dd];
__device__ __align__(16) __half g_yH[M1*Dd];
__device__ __align__(16) __half g_wH[4521984]; // all weights fp16

// g_wH element offsets (QS,KS,VS contiguous; KC,VC contiguous)
#define W_QS 0
#define W_KS 16384
#define W_VS 32768
#define W_OS 49152
#define W_QC 65536
#define W_KC 81920
#define W_VC 98304
#define W_OC 114688
#define W_W1 131072
#define W_W2 196608
#define W_W3 262144
#define W_GW 327680
#define W_SUP 4259840

__device__ __forceinline__ uint32_t h2u(__half2 h) {
    uint32_t u; memcpy(&u, &h, 4); return u;
}
__device__ __forceinline__ void cvt8(float* f, uint4 u) {
    uint32_t w[4] = {u.x, u.y, u.z, u.w};
    #pragma unroll
    for (int i = 0; i < 4; i++) {
        __half2 h; memcpy(&h, &w[i], 4);
        float2 g = __half22float2(h);
        f[2*i] = g.x; f[2*i+1] = g.y;
    }
}
__device__ __forceinline__ uint32_t s2u(const void* p) {
    return (uint32_t)__cvta_generic_to_shared(p);
}
#define CPA16(dst, src) asm volatile("cp.async.cg.shared.global [%0], [%1], 16;\n" :: "r"(dst), "l"(src))
#define CPCOMMIT()      asm volatile("cp.async.commit_group;\n" ::: "memory")

// ---------------- cp.async + ldmatrix fp16 GEMM, 3-stage pipeline ----------------
// C = A@B (+bias)(+relu). A[M,K] fp16, B[K,N] fp16.
// CH: 0 fp32 C; 1 fp16 C; 2 both (C2 fp16); 3 fp32 transposed C with per-row bias
//     (D[M,N] stored as C[z][n][m], bias = biasPtr + za*sBias indexed by m).
// Per batch z: za=(modA? z%modA : z); A += za*sA ; B += z*sB ; C += z*sC.
#define STAGE 32768
#define GSMEM (3*STAGE)

template<int CH>
__global__ void __launch_bounds__(256, 2) hgemm_kernel(
    const __half* __restrict__ A, const __half* __restrict__ B,
    void* __restrict__ Cv, __half* __restrict__ C2,
    int M, int N, int K,
    long long sA, long long sB, long long sC, int modA,
    const float* __restrict__ bias, long long sBias, int doRelu)
{
    extern __shared__ char smem[];
    uint32_t sb = s2u(smem);

    int z = blockIdx.z;
    long long za = (modA > 0 ? (z % modA) : z);
    const __half* Ag = A + za * sA + (long long)blockIdx.y * 128 * K;
    const __half* Bg = B + (long long)z * sB;

    int tid = threadIdx.x;
    int warp = tid >> 5, lane = tid & 31;
    int wm = warp >> 2, wn = warp & 3;
    int lr = lane >> 2, lc = lane & 3;
    int brow = blockIdx.y * 128, bcol = blockIdx.x * 128;

    int aRowL = (lane & 7) + ((lane >> 3) & 1) * 8;
    int aKcL  = lane >> 4;
    int bKL   = (lane & 7) + ((lane >> 3) & 1) * 8;
    int bNcL  = lane >> 4;

    float acc[4][4][4];
    #pragma unroll
    for (int i = 0; i < 4; i++)
        #pragma unroll
        for (int j = 0; j < 4; j++)
            #pragma unroll
            for (int r = 0; r < 4; r++) acc[i][j][r] = 0.f;

    int nC = K >> 6;

    auto issue = [&](int ct, int bo) {
        uint32_t abase = sb + bo;
        const __half* ap = Ag + ct * 64;
        #pragma unroll
        for (int u = 0; u < 4; u++) {
            int r = u*32 + (tid >> 3);
            int cc = tid & 7;
            uint32_t dst = abase + r*128 + ((cc ^ (r & 7)) << 4);
            CPA16(dst, ap + (long long)r * K + cc*8);
        }
        uint32_t bbase = abase + 16384;
        const __half* bp = Bg + (long long)(ct*64) * N + bcol;
        #pragma unroll
        for (int u = 0; u < 4; u++) {
            int k = u*16 + (tid >> 4);
            int cc = tid & 15;
            uint32_t dst = bbase + k*256 + (((cc & 8) | ((cc & 7) ^ (k & 7))) << 4);
            CPA16(dst, bp + (long long)k * N + cc*8);
        }
        CPCOMMIT();
    };

    auto compute = [&](int bo) {
        uint32_t abase = sb + bo;
        uint32_t bbase = abase + 16384;
        #pragma unroll
        for (int kk = 0; kk < 4; kk++) {
            uint32_t af[4][4];
            #pragma unroll
            for (int mf = 0; mf < 4; mf++) {
                int row = wm*64 + mf*16 + aRowL;
                int kc = kk*2 + aKcL;
                uint32_t ad = abase + row*128 + ((kc ^ (row & 7)) << 4);
                asm volatile("ldmatrix.sync.aligned.m8n8.x4.shared.b16 {%0,%1,%2,%3}, [%4];\n"
                    : "=r"(af[mf][0]), "=r"(af[mf][1]), "=r"(af[mf][2]), "=r"(af[mf][3]) : "r"(ad));
            }
            uint32_t bf[4][2];
            #pragma unroll
            for (int np = 0; np < 2; np++) {
                int k = kk*16 + bKL;
                int nc = wn*4 + np*2 + bNcL;
                uint32_t bd = bbase + k*256 + (((nc & 8) | ((nc & 7) ^ (k & 7))) << 4);
                asm volatile("ldmatrix.sync.aligned.m8n8.x4.trans.shared.b16 {%0,%1,%2,%3}, [%4];\n"
                    : "=r"(bf[2*np][0]), "=r"(bf[2*np][1]), "=r"(bf[2*np+1][0]), "=r"(bf[2*np+1][1]) : "r"(bd));
            }
            #pragma unroll
            for (int mf = 0; mf < 4; mf++)
                #pragma unroll
                for (int nf = 0; nf < 4; nf++) {
                    asm volatile(
                        "mma.sync.aligned.m16n8k16.row.col.f32.f16.f16.f32 "
                        "{%0,%1,%2,%3}, {%4,%5,%6,%7}, {%8,%9}, {%0,%1,%2,%3};\n"
                        : "+f"(acc[mf][nf][0]), "+f"(acc[mf][nf][1]),
                          "+f"(acc[mf][nf][2]), "+f"(acc[mf][nf][3])
                        : "r"(af[mf][0]), "r"(af[mf][1]), "r"(af[mf][2]), "r"(af[mf][3]),
                          "r"(bf[nf][0]), "r"(bf[nf][1]));
                }
        }
    };

    issue(0, 0);
    if (nC > 1) issue(1, STAGE);
    for (int c = 0; c < nC; c++) {
        if (c == nC - 1) { asm volatile("cp.async.wait_group 0;\n" ::: "memory"); }
        else             { asm volatile("cp.async.wait_group 1;\n" ::: "memory"); }
        __syncthreads();
        compute((c % 3) * STAGE);
        if (c + 2 < nC) issue(c + 2, ((c + 2) % 3) * STAGE);
    }

    if (CH == 3) {
        // transposed fp32 epilogue with per-row (m) bias: C[z][n][m]
        __syncthreads();
        float* stg = (float*)smem;   // [128 m][129]
        #pragma unroll
        for (int mf = 0; mf < 4; mf++) {
            int r0 = wm*64 + mf*16 + lr;
            #pragma unroll
            for (int nf = 0; nf < 4; nf++) {
                int c0 = wn*32 + nf*8 + lc*2;
                stg[r0*129 + c0]       = acc[mf][nf][0];
                stg[r0*129 + c0 + 1]   = acc[mf][nf][1];
                stg[(r0+8)*129 + c0]   = acc[mf][nf][2];
                stg[(r0+8)*129 + c0+1] = acc[mf][nf][3];
            }
        }
        __syncthreads();
        int n = tid >> 1, o0 = (tid & 1) * 64;
        const float* bz = bias + za * sBias;
        float* op = (float*)Cv + (long long)z * sC + (long long)(bcol + n) * M + brow + o0;
        #pragma unroll 4
        for (int j = 0; j < 64; j += 4) {
            float4 v;
            v.x = stg[(o0+j+0)*129 + n] + bz[brow + o0 + j + 0];
            v.y = stg[(o0+j+1)*129 + n] + bz[brow + o0 + j + 1];
            v.z = stg[(o0+j+2)*129 + n] + bz[brow + o0 + j + 2];
            v.w = stg[(o0+j+3)*129 + n] + bz[brow + o0 + j + 3];
            *(float4*)(op + j) = v;
        }
        return;
    }

    #pragma unroll
    for (int mf = 0; mf < 4; mf++) {
        int row0 = brow + wm*64 + mf*16 + lr;
        #pragma unroll
        for (int nf = 0; nf < 4; nf++) {
            int col = bcol + wn*32 + nf*8 + lc*2;
            float bx = 0.f, by = 0.f;
            if (bias) { bx = bias[col]; by = bias[col+1]; }
            float v0 = acc[mf][nf][0] + bx;
            float v1 = acc[mf][nf][1] + by;
            float v2 = acc[mf][nf][2] + bx;
            float v3 = acc[mf][nf][3] + by;
            if (doRelu) {
                v0 = fmaxf(v0, 0.f); v1 = fmaxf(v1, 0.f);
                v2 = fmaxf(v2, 0.f); v3 = fmaxf(v3, 0.f);
            }
            if (CH == 0 || CH == 2) {
                float* Cf = (float*)Cv + (long long)z * sC;
                *(float2*)(Cf + (long long)row0*N + col)     = make_float2(v0, v1);
                *(float2*)(Cf + (long long)(row0+8)*N + col) = make_float2(v2, v3);
            }
            if (CH == 1) {
                __half* Ch = (__half*)Cv + (long long)z * sC;
                *(__half2*)(Ch + (long long)row0*N + col)     = __floats2half2_rn(v0, v1);
                *(__half2*)(Ch + (long long)(row0+8)*N + col) = __floats2half2_rn(v2, v3);
            }
            if (CH == 2) {
                *(__half2*)(C2 + (long long)row0*N + col)     = __floats2half2_rn(v0, v1);
                *(__half2*)(C2 + (long long)(row0+8)*N + col) = __floats2half2_rn(v2, v3);
            }
        }
    }
}

// ---------------- attention: fp16 Q/K/V/O (R10 proven) ----------------
#define STP 52
__global__ void __launch_bounds__(256) attn_kernel(
    const __half* __restrict__ Q, const __half* __restrict__ Kt, const __half* __restrict__ V,
    __half* __restrict__ O, int Lq, int Lk)
{
    __shared__ uint32_t Qs[48*12];
    __shared__ uint32_t Ks[96*12];
    __shared__ uint32_t Vs[96*12];
    __shared__ float St[96*STP];

    int bid = blockIdx.x;
    int h = bid & 7;
    int n = (bid >> 3) & (Nn - 1);
    int b = bid >> 12;
    int tid = threadIdx.x;

    for (int i = tid; i < Lq*4; i += 256) {
        int l = i >> 2, j = i & 3;
        uint2 v = *(const uint2*)(Q + (((long long)(b*Lq + l))*Nn + n)*Dd + h*HD + j*4);
        Qs[l*12 + j*2]     = v.x;
        Qs[l*12 + j*2 + 1] = v.y;
    }
    for (int i = tid; i < Lk*4; i += 256) {
        int m = i >> 2, j = i & 3;
        long long base = (((long long)(b*Lk + m))*Nn + n)*Dd + h*HD + j*4;
        uint2 vk = *(const uint2*)(Kt + base);
        uint2 vv = *(const uint2*)(V + base);
        Ks[m*12 + j*2]     = vk.x;
        Ks[m*12 + j*2 + 1] = vk.y;
        Vs[m*12 + j*2]     = vv.x;
        Vs[m*12 + j*2 + 1] = vv.y;
    }
    __syncthreads();

    const float scale = 0.25f;
    int tlc = Lq >> 1, tmc = Lk >> 2;
    for (int t = tid; t < tlc*tmc; t += 256) {
        int tl = t % tlc, tm = t / tlc;
        int l0 = tl*2, m0 = tm*4;
        float qa[16], qb[16];
        cvt8(qa,     *(const uint4*)&Qs[l0*12]);
        cvt8(qa + 8, *(const uint4*)&Qs[l0*12 + 4]);
        cvt8(qb,     *(const uint4*)&Qs[(l0+1)*12]);
        cvt8(qb + 8, *(const uint4*)&Qs[(l0+1)*12 + 4]);
        #pragma unroll
        for (int mi = 0; mi < 4; mi++) {
            float kv[16];
            cvt8(kv,     *(const uint4*)&Ks[(m0+mi)*12]);
            cvt8(kv + 8, *(const uint4*)&Ks[(m0+mi)*12 + 4]);
            float sA = 0.f, sB = 0.f;
            #pragma unroll
            for (int j = 0; j < 16; j++) {
                sA = fmaf(qa[j], kv[j], sA);
                sB = fmaf(qb[j], kv[j], sB);
            }
            St[(m0+mi)*STP + l0]     = sA * scale;
            St[(m0+mi)*STP + l0 + 1] = sB * scale;
        }
    }
    __syncthreads();

    if (tid < Lq) {
        float mx = -1e30f;
        for (int m = 0; m < Lk; m++) mx = fmaxf(mx, St[m*STP + tid]);
        float sum = 0.f;
        for (int m = 0; m < Lk; m++) {
            float e = __expf(St[m*STP + tid] - mx);
            St[m*STP + tid] = e;
            sum += e;
        }
        float inv = 1.f / sum;
        for (int m = 0; m < Lk; m++) St[m*STP + tid] *= inv;
    }
    __syncthreads();

    if (tid < Lq * 2) {
        int l = tid >> 1, j8 = tid & 1;
        float a[8];
        #pragma unroll
        for (int j = 0; j < 8; j++) a[j] = 0.f;
        for (int m = 0; m < Lk; m++) {
            float v[8];
            cvt8(v, *(const uint4*)&Vs[m*12 + j8*4]);
            float w = St[m*STP + l];
            #pragma unroll
            for (int j = 0; j < 8; j++) a[j] = fmaf(w, v[j], a[j]);
        }
        uint4 o;
        o.x = h2u(__floats2half2_rn(a[0], a[1]));
        o.y = h2u(__floats2half2_rn(a[2], a[3]));
        o.z = h2u(__floats2half2_rn(a[4], a[5]));
        o.w = h2u(__floats2half2_rn(a[6], a[7]));
        *(uint4*)(O + (((long long)(b*Lq + l))*Nn + n)*Dd + h*HD + j8*8) = o;
    }
}

// ---------------- residual add + LayerNorm (optional fp16 dual output) ----------------
template<int DUAL>
__global__ void __launch_bounds__(256) ln_add_kernel(
    float* __restrict__ out, __half* __restrict__ outH,
    const float* __restrict__ X, const float* __restrict__ P,
    const float* __restrict__ g, const float* __restrict__ bta, int rows)
{
    int row  = (blockIdx.x * 256 + threadIdx.x) >> 5;
    int lane = threadIdx.x & 31;
    if (row >= rows) return;
    long long base = (long long)row * Dd + lane*4;
    float4 a = *(const float4*)(X + base);
    float4 p = *(const float4*)(P + base);
    float v0 = a.x+p.x, v1 = a.y+p.y, v2 = a.z+p.z, v3 = a.w+p.w;
    float s  = v0+v1+v2+v3;
    float s2 = v0*v0+v1*v1+v2*v2+v3*v3;
    #pragma unroll
    for (int o = 16; o; o >>= 1) {
        s  += __shfl_xor_sync(0xffffffffu, s,  o);
        s2 += __shfl_xor_sync(0xffffffffu, s2, o);
    }
    float mu  = s * (1.f/128.f);
    float var = s2 * (1.f/128.f) - mu*mu;
    float rs  = rsqrtf(var + 1e-5f);
    float4 gg = *(const float4*)(g   + lane*4);
    float4 bb = *(const float4*)(bta + lane*4);
    float4 o4;
    o4.x = (v0-mu)*rs*gg.x + bb.x;
    o4.y = (v1-mu)*rs*gg.y + bb.y;
    o4.z = (v2-mu)*rs*gg.z + bb.z;
    o4.w = (v3-mu)*rs*gg.w + bb.w;
    *(float4*)(out + base) = o4;
    if (DUAL) {
        uint2 hp = make_uint2(h2u(__floats2half2_rn(o4.x, o4.y)),
                              h2u(__floats2half2_rn(o4.z, o4.w)));
        *(uint2*)(outH + base) = hp;
    }
}

// ---------------- transpose data[bl] [512,128] -> fp16 g0 rows of Hc [128,512] ----------------
__global__ void transpose_g0_kernel(const float* __restrict__ in, __half* __restrict__ out)
{
    __shared__ float t[32][33];
    int bl = blockIdx.z;
    int n0 = blockIdx.x * 32;
    int c0 = blockIdx.y * 32;
    const float* ip = in  + (long long)bl * (Nn*Dd);
    __half*      op = out + (long long)bl * (640*Nn);
    #pragma unroll
    for (int j = 0; j < 32; j += 8)
        t[threadIdx.y + j][threadIdx.x] = ip[(n0 + threadIdx.y + j)*Dd + c0 + threadIdx.x];
    __syncthreads();
    #pragma unroll
    for (int j = 0; j < 32; j += 8)
        op[(c0 + threadIdx.y + j)*Nn + n0 + threadIdx.x] = __float2half(t[threadIdx.x][threadIdx.y + j]);
}

// ---------------- fp32 -> fp16 convert ----------------
__global__ void f2h_kernel(const float* __restrict__ in, __half* __restrict__ out, int n4)
{
    int i = blockIdx.x * 256 + threadIdx.x;
    if (i < n4) {
        float4 v = ((const float4*)in)[i];
        ((uint2*)out)[i] = make_uint2(h2u(__floats2half2_rn(v.x, v.y)),
                                      h2u(__floats2half2_rn(v.z, v.w)));
    }
}

// ---------------- host ----------------
template<int CH>
static inline void gemmT(const __half* A, const __half* B, void* C, __half* C2,
                         int M, int N, int K,
                         long long sA, long long sB, long long sC, int batch, int modA,
                         const float* bias, long long sBias, int relu)
{
    dim3 grid(N/128, M/128, batch);
    hgemm_kernel<CH><<<grid, 256, GSMEM>>>(A, B, C, C2, M, N, K, sA, sB, sC, modA, bias, sBias, relu);
}

static inline void f2h(const float* in, __half* out, long long n)
{
    int n4 = (int)(n / 4);
    f2h_kernel<<<(n4 + 255)/256, 256>>>(in, out, n4);
}

extern "C" void kernel_launch(void* const* d_in, const int* in_sizes, int n_in,
                              void* d_out, int out_size)
{
    const float* x       = (const float*)d_in[0];
    const float* memory  = (const float*)d_in[1];
    const float* data    = (const float*)d_in[2];
    const float* support = (const float*)d_in[3];
    const float* Ws[8]   = { (const float*)d_in[4], (const float*)d_in[5],
                             (const float*)d_in[6], (const float*)d_in[7],
                             (const float*)d_in[8], (const float*)d_in[9],
                             (const float*)d_in[10], (const float*)d_in[11] };
    const float* W1   = (const float*)d_in[12];
    const float* b1   = (const float*)d_in[13];
    const float* W2   = (const float*)d_in[14];
    const float* b2   = (const float*)d_in[15];
    const float* W3   = (const float*)d_in[16];
    const float* b3   = (const float*)d_in[17];
    const float* gcnW = (const float*)d_in[18];
    const float* gcnB = (const float*)d_in[19];
    const float* ln1g = (const float*)d_in[20];
    const float* ln1b = (const float*)d_in[21];
    const float* ln2g = (const float*)d_in[22];
    const float* ln2b = (const float*)d_in[23];
    const float* ln3g = (const float*)d_in[24];
    const float* ln3b = (const float*)d_in[25];

    float *q, *t, *h, *xn, *y;
    __half *bigH, *HbH, *xH, *memH, *qkvH, *kvH, *qH, *tH, *xnH, *yH, *wH;
    cudaGetSymbolAddress((void**)&q,  g_q);
    cudaGetSymbolAddress((void**)&t,  g_t);
    cudaGetSymbolAddress((void**)&h,  g_h);
    cudaGetSymbolAddress((void**)&xn, g_xn);
    cudaGetSymbolAddress((void**)&y,  g_y);
    cudaGetSymbolAddress((void**)&bigH, g_bigH);
    cudaGetSymbolAddress((void**)&HbH, g_HbH);
    cudaGetSymbolAddress((void**)&xH, g_xH);
    cudaGetSymbolAddress((void**)&memH, g_memH);
    cudaGetSymbolAddress((void**)&qkvH, g_qkvH);
    cudaGetSymbolAddress((void**)&kvH, g_kvH);
    cudaGetSymbolAddress((void**)&qH, g_qH);
    cudaGetSymbolAddress((void**)&tH, g_tH);
    cudaGetSymbolAddress((void**)&xnH, g_xnH);
    cudaGetSymbolAddress((void**)&yH, g_yH);
    cudaGetSymbolAddress((void**)&wH, g_wH);

    cudaFuncSetAttribute(hgemm_kernel<0>, cudaFuncAttributeMaxDynamicSharedMemorySize, GSMEM);
    cudaFuncSetAttribute(hgemm_kernel<1>, cudaFuncAttributeMaxDynamicSharedMemorySize, GSMEM);
    cudaFuncSetAttribute(hgemm_kernel<2>, cudaFuncAttributeMaxDynamicSharedMemorySize, GSMEM);
    cudaFuncSetAttribute(hgemm_kernel<3>, cudaFuncAttributeMaxDynamicSharedMemorySize, GSMEM);

    float* out1 = (float*)d_out;               // LN3(xn + y)
    float* out2 = out1 + (long long)M1 * Dd;   // dts

    const int nLn = M1 / 8;
    const long long S1 = (long long)M1 * Dd;   // 12582912
    const long long S2 = (long long)M2 * Dd;

    // ---- fp16 conversions ----
    f2h(x, xH, S1);
    f2h(memory, memH, S2);
    int wOff[8] = { W_QS, W_KS, W_VS, W_OS, W_QC, W_KC, W_VC, W_OC };
    for (int i = 0; i < 8; i++) f2h(Ws[i], wH + wOff[i], 16384);
    f2h(W1, wH + W_W1, 65536);
    f2h(W2, wH + W_W2, 65536);
    f2h(W3, wH + W_W3, 65536);
    f2h(gcnW, wH + W_GW, (long long)Ll*Dd*640);
    f2h(support, wH + W_SUP, Nn*Nn);

    // ---- self-attention (batched QKV: Wq/Wk/Wv contiguous in wH) ----
    gemmT<1>(xH, wH+W_QS, qkvH, 0, M1,128,128, 0,16384,S1, 3,1, nullptr,0, 0);
    attn_kernel<<<Bb*Nn*Hh, 256>>>(qkvH, qkvH + S1, qkvH + 2*S1, tH, Ll, Ll);
    gemmT<0>(tH, wH+W_OS, q, 0, M1,128,128, 0,0,0, 1,0, nullptr,0, 0);
    ln_add_kernel<1><<<nLn, 256>>>(h, tH, x, q, ln1g, ln1b, M1);    // hH = tH

    // ---- cross-attention (batched KV) ----
    gemmT<1>(tH,   wH+W_QC, qH,  0, M1,128,128, 0,0,0, 1,0, nullptr,0, 0);
    gemmT<1>(memH, wH+W_KC, kvH, 0, M2,128,128, 0,16384,S2, 2,1, nullptr,0, 0);
    attn_kernel<<<Bb*Nn*Hh, 256>>>(qH, kvH, kvH + S2, tH, Ll, LP);
    gemmT<0>(tH, wH+W_OC, t, 0, M1,128,128, 0,0,0, 1,0, nullptr,0, 0);
    ln_add_kernel<1><<<nLn, 256>>>(xn, xnH, h, t, ln2g, ln2b, M1);

    // ---- FFN (y1 fp16; y dual fp32+fp16) ----
    gemmT<1>(xnH,  wH+W_W1, bigH, 0,  M1,512,128, 0,0,0, 1,0, b1,0, 1);
    gemmT<2>(bigH, wH+W_W2, y,    yH, M1,128,512, 0,0,0, 1,0, b2,0, 0);
    ln_add_kernel<0><<<nLn, 256>>>(out1, 0, xn, y, ln3g, ln3b, M1);

    // ---- dynamic adjacency A = y@W3 + b3 (fp16) ----
    gemmT<1>(yH, wH+W_W3, bigH, 0, M1,512,128, 0,0,0, 1,0, b3,0, 0);

    // ---- GCN (all fp16; final GEMM writes dts directly via transposed epilogue) ----
    transpose_g0_kernel<<<dim3(16,4,BLn), dim3(32,8)>>>(data, HbH);
    gemmT<1>(HbH,          wH+W_SUP, HbH +  65536, 0, 128,512,512, 327680,0,      327680, BLn,0, nullptr,0, 0);
    gemmT<1>(HbH,          bigH,     HbH + 196608, 0, 128,512,512, 327680,262144, 327680, BLn,0, nullptr,0, 0);
    gemmT<1>(HbH +  65536, wH+W_SUP, HbH + 131072, 0, 128,512,512, 327680,0,      327680, BLn,0, nullptr,0, 0);
    gemmT<1>(HbH + 196608, bigH,     HbH + 262144, 0, 128,512,512, 327680,262144, 327680, BLn,0, nullptr,0, 0);
    gemmT<3>(wH+W_GW, HbH, out2, 0, 128,512,640, 81920,327680,65536, BLn,Ll, gcnB,128, 0);
}